// round 1
// baseline (speedup 1.0000x reference)
#include <cuda_runtime.h>

#define B_     16
#define C_     512
#define S_     1024
#define H_     8
#define DH_    64
#define N3_    1536
#define INNER_ 512
#define SCALE_ 0.125f

// Scratch (allocation-free rule: __device__ globals)
__device__ float g_qkv[(size_t)B_ * S_ * N3_];    // (b, s, 1536)
__device__ float g_res[(size_t)B_ * S_ * INNER_]; // (b, s, 512)

// ---------------------------------------------------------------------------
// GEMM1: qkv[b][s][n] = sum_c x[b][c][s] * W_proj[c][n] + b_proj[n]
// 128x128 tile, BK=8, 8x8 per thread
// ---------------------------------------------------------------------------
__global__ __launch_bounds__(256) void gemm_qkv_kernel(
    const float* __restrict__ x, const float* __restrict__ W,
    const float* __restrict__ bias)
{
    __shared__ float As[8][128];
    __shared__ float Bs[8][128];

    const int b  = blockIdx.z;
    const int m0 = blockIdx.x * 128;   // s tile
    const int n0 = blockIdx.y * 128;   // n tile
    const float* xb = x + (size_t)b * C_ * S_;

    float acc[8][8];
#pragma unroll
    for (int i = 0; i < 8; i++)
#pragma unroll
        for (int j = 0; j < 8; j++) acc[i][j] = 0.f;

    const int tid = threadIdx.x;
    const int tx = tid & 15, ty = tid >> 4;

    for (int k0 = 0; k0 < C_; k0 += 8) {
#pragma unroll
        for (int i = 0; i < 4; i++) {
            int idx = tid + i * 256;
            int kk = idx >> 7, mm = idx & 127;
            As[kk][mm] = xb[(size_t)(k0 + kk) * S_ + m0 + mm];     // coalesced in s
            Bs[kk][mm] = W[(size_t)(k0 + kk) * N3_ + n0 + mm];     // coalesced in n
        }
        __syncthreads();
#pragma unroll
        for (int kk = 0; kk < 8; kk++) {
            float a[8], bb[8];
#pragma unroll
            for (int i = 0; i < 8; i++) a[i] = As[kk][ty * 8 + i];
#pragma unroll
            for (int j = 0; j < 8; j++) bb[j] = Bs[kk][tx * 8 + j];
#pragma unroll
            for (int i = 0; i < 8; i++)
#pragma unroll
                for (int j = 0; j < 8; j++) acc[i][j] += a[i] * bb[j];
        }
        __syncthreads();
    }

#pragma unroll
    for (int i = 0; i < 8; i++) {
        int m = m0 + ty * 8 + i;
#pragma unroll
        for (int j = 0; j < 8; j++) {
            int n = n0 + tx * 8 + j;
            g_qkv[((size_t)b * S_ + m) * N3_ + n] = acc[i][j] + bias[n];
        }
    }
}

// ---------------------------------------------------------------------------
// Attention: per (b, h, 64-query tile). Flash-style online softmax over
// 16 key tiles of 64. 256 threads; thread (ty,tx) owns 4 rows x 4 cols.
// Dynamic smem: Qs[64][64], Ks[64][65] (padded), Vs[64][64], Ps[64][64]
// ---------------------------------------------------------------------------
__global__ __launch_bounds__(256) void attn_kernel()
{
    extern __shared__ float sm[];
    float (*Qs)[64] = (float (*)[64])(sm);
    float (*Ks)[65] = (float (*)[65])(sm + 64 * 64);
    float (*Vs)[64] = (float (*)[64])(sm + 64 * 64 + 64 * 65);
    float (*Ps)[64] = (float (*)[64])(sm + 64 * 64 + 64 * 65 + 64 * 64);

    const int b  = blockIdx.z;
    const int h  = blockIdx.y;
    const int q0 = blockIdx.x * 64;
    const int tid = threadIdx.x;
    const int tx = tid & 15, ty = tid >> 4;

    const float* base = g_qkv + (size_t)b * S_ * N3_ + h * 192;

    // Load Q tile (64x64), float4 vectorized
#pragma unroll
    for (int i = 0; i < 4; i++) {
        int idx = tid + i * 256;          // float4 index 0..1023
        int r = idx >> 4;
        int d4 = (idx & 15) << 2;
        float4 v = *(const float4*)(base + (size_t)(q0 + r) * N3_ + d4);
        Qs[r][d4] = v.x; Qs[r][d4 + 1] = v.y; Qs[r][d4 + 2] = v.z; Qs[r][d4 + 3] = v.w;
    }

    float m_i[4], l_i[4], o[4][4];
#pragma unroll
    for (int i = 0; i < 4; i++) {
        m_i[i] = -1e30f; l_i[i] = 0.f;
#pragma unroll
        for (int j = 0; j < 4; j++) o[i][j] = 0.f;
    }

    for (int kt = 0; kt < 16; kt++) {
        __syncthreads();  // prev accumulate done before overwriting K/V
#pragma unroll
        for (int i = 0; i < 4; i++) {
            int idx = tid + i * 256;
            int r = idx >> 4;
            int d4 = (idx & 15) << 2;
            const float* p = base + (size_t)(kt * 64 + r) * N3_ + 64 + d4;
            float4 kv = *(const float4*)p;
            Ks[r][d4] = kv.x; Ks[r][d4 + 1] = kv.y; Ks[r][d4 + 2] = kv.z; Ks[r][d4 + 3] = kv.w;
            float4 vv = *(const float4*)(p + 64);
            Vs[r][d4] = vv.x; Vs[r][d4 + 1] = vv.y; Vs[r][d4 + 2] = vv.z; Vs[r][d4 + 3] = vv.w;
        }
        __syncthreads();

        // Scores: 4x4 register tile
        float sc[4][4];
#pragma unroll
        for (int i = 0; i < 4; i++)
#pragma unroll
            for (int j = 0; j < 4; j++) sc[i][j] = 0.f;

        for (int d = 0; d < 64; d++) {
            float qv[4], kv[4];
#pragma unroll
            for (int i = 0; i < 4; i++) qv[i] = Qs[ty * 4 + i][d];
#pragma unroll
            for (int j = 0; j < 4; j++) kv[j] = Ks[tx * 4 + j][d];
#pragma unroll
            for (int i = 0; i < 4; i++)
#pragma unroll
                for (int j = 0; j < 4; j++) sc[i][j] += qv[i] * kv[j];
        }

        // Online softmax per row i (16 tx-threads per row; lanes tx within warp)
#pragma unroll
        for (int i = 0; i < 4; i++) {
#pragma unroll
            for (int j = 0; j < 4; j++) sc[i][j] *= SCALE_;
            float tmax = fmaxf(fmaxf(sc[i][0], sc[i][1]), fmaxf(sc[i][2], sc[i][3]));
            tmax = fmaxf(tmax, __shfl_xor_sync(0xffffffffu, tmax, 1));
            tmax = fmaxf(tmax, __shfl_xor_sync(0xffffffffu, tmax, 2));
            tmax = fmaxf(tmax, __shfl_xor_sync(0xffffffffu, tmax, 4));
            tmax = fmaxf(tmax, __shfl_xor_sync(0xffffffffu, tmax, 8));
            float mn = fmaxf(m_i[i], tmax);
            float f = __expf(m_i[i] - mn);
            float ps = 0.f;
#pragma unroll
            for (int j = 0; j < 4; j++) {
                float p = __expf(sc[i][j] - mn);
                Ps[ty * 4 + i][tx * 4 + j] = p;
                ps += p;
            }
            ps += __shfl_xor_sync(0xffffffffu, ps, 1);
            ps += __shfl_xor_sync(0xffffffffu, ps, 2);
            ps += __shfl_xor_sync(0xffffffffu, ps, 4);
            ps += __shfl_xor_sync(0xffffffffu, ps, 8);
            l_i[i] = l_i[i] * f + ps;
            m_i[i] = mn;
#pragma unroll
            for (int j = 0; j < 4; j++) o[i][j] *= f;
        }
        __syncthreads();  // Ps visible

        // Accumulate O += P @ V (4x4 register tile)
        for (int j = 0; j < 64; j++) {
            float pv[4], vv[4];
#pragma unroll
            for (int i = 0; i < 4; i++) pv[i] = Ps[ty * 4 + i][j];
#pragma unroll
            for (int jj = 0; jj < 4; jj++) vv[jj] = Vs[j][tx * 4 + jj];
#pragma unroll
            for (int i = 0; i < 4; i++)
#pragma unroll
                for (int jj = 0; jj < 4; jj++) o[i][jj] += pv[i] * vv[jj];
        }
    }

    // Write res[b][q][h*64 + d]
#pragma unroll
    for (int i = 0; i < 4; i++) {
        float inv = 1.f / l_i[i];
        size_t off = ((size_t)b * S_ + q0 + ty * 4 + i) * INNER_ + h * 64 + tx * 4;
#pragma unroll
        for (int jj = 0; jj < 4; jj++) g_res[off + jj] = o[i][jj] * inv;
    }
}

// ---------------------------------------------------------------------------
// GEMM3: out[b][c][s] = sum_k res[b][s][k] * W_out[k][c] + b_out[c] + x[b][c][s]
// M = c (rows), N = s (cols) -> coalesced output stores.
// ---------------------------------------------------------------------------
__global__ __launch_bounds__(256) void gemm_out_kernel(
    const float* __restrict__ Wo, const float* __restrict__ bo,
    const float* __restrict__ x, float* __restrict__ out)
{
    __shared__ float As[8][128];
    __shared__ float Bs[8][128];

    const int b  = blockIdx.z;
    const int c0 = blockIdx.x * 128;
    const int s0 = blockIdx.y * 128;

    float acc[8][8];
#pragma unroll
    for (int i = 0; i < 8; i++)
#pragma unroll
        for (int j = 0; j < 8; j++) acc[i][j] = 0.f;

    const int tid = threadIdx.x;
    const int tx = tid & 15, ty = tid >> 4;
    const float* resb = g_res + (size_t)b * S_ * INNER_;

    for (int k0 = 0; k0 < INNER_; k0 += 8) {
#pragma unroll
        for (int i = 0; i < 4; i++) {
            int idx = tid + i * 256;
            int kk = idx >> 7, cc = idx & 127;
            As[kk][cc] = Wo[(size_t)(k0 + kk) * C_ + c0 + cc];   // coalesced in c
        }
#pragma unroll
        for (int i = 0; i < 2; i++) {
            int idx2 = tid + i * 256;           // 0..511 float2 slots
            int nn = idx2 >> 2, kp = idx2 & 3;
            float2 v = *(const float2*)(resb + (size_t)(s0 + nn) * INNER_ + k0 + kp * 2);
            Bs[kp * 2][nn]     = v.x;
            Bs[kp * 2 + 1][nn] = v.y;
        }
        __syncthreads();
#pragma unroll
        for (int kk = 0; kk < 8; kk++) {
            float a[8], bb[8];
#pragma unroll
            for (int i = 0; i < 8; i++) a[i] = As[kk][ty * 8 + i];
#pragma unroll
            for (int j = 0; j < 8; j++) bb[j] = Bs[kk][tx * 8 + j];
#pragma unroll
            for (int i = 0; i < 8; i++)
#pragma unroll
                for (int j = 0; j < 8; j++) acc[i][j] += a[i] * bb[j];
        }
        __syncthreads();
    }

    const float* xb = x + (size_t)b * C_ * S_;
    float* ob = out + (size_t)b * C_ * S_;
#pragma unroll
    for (int i = 0; i < 8; i++) {
        int c = c0 + ty * 8 + i;
        float bias = bo[c];
#pragma unroll
        for (int j = 0; j < 8; j++) {
            int s = s0 + tx * 8 + j;
            ob[(size_t)c * S_ + s] = acc[i][j] + bias + xb[(size_t)c * S_ + s];
        }
    }
}

// ---------------------------------------------------------------------------
extern "C" void kernel_launch(void* const* d_in, const int* in_sizes, int n_in,
                              void* d_out, int out_size)
{
    const float* x  = (const float*)d_in[0];
    const float* Wp = (const float*)d_in[1];
    const float* bp = (const float*)d_in[2];
    const float* Wo = (const float*)d_in[3];
    const float* bo = (const float*)d_in[4];
    float* out = (float*)d_out;

    // Attention needs 65,792 B dynamic smem (> 48KB default) — opt in each call
    // (idempotent, immediate host-side call; not a stream op, graph-safe).
    static const int attn_smem = (64 * 64 + 64 * 65 + 64 * 64 + 64 * 64) * (int)sizeof(float);
    cudaFuncSetAttribute(attn_kernel, cudaFuncAttributeMaxDynamicSharedMemorySize, attn_smem);

    // Stage 1: QKV projection
    gemm_qkv_kernel<<<dim3(S_ / 128, N3_ / 128, B_), 256>>>(x, Wp, bp);

    // Stage 2: fused attention
    attn_kernel<<<dim3(S_ / 64, H_, B_), 256, attn_smem>>>();

    // Stage 3: output projection + bias + residual + transpose
    gemm_out_kernel<<<dim3(C_ / 128, S_ / 128, B_), 256>>>(Wo, bo, x, out);
}

// round 2
// speedup vs baseline: 3.2116x; 3.2116x over previous
#include <cuda_runtime.h>

#define B_     16
#define C_     512
#define S_     1024
#define H_     8
#define DH_    64
#define N3_    1536
#define INNER_ 512
#define SCALE_ 0.125f

// Scratch (allocation-free rule: __device__ globals)
__device__ float g_qkv[(size_t)B_ * S_ * N3_];    // (b, s, 1536)
__device__ float g_res[(size_t)B_ * S_ * INNER_]; // (b, s, 512)

// ---------------------------------------------------------------------------
// tf32 helpers
// ---------------------------------------------------------------------------
__device__ __forceinline__ unsigned f2tf(float f) {
    unsigned u;
    asm("cvt.rna.tf32.f32 %0, %1;" : "=r"(u) : "f"(f));
    return u;
}

// D += A(16x8, row) * B(8x8, col)  tf32 -> f32
__device__ __forceinline__ void mma8(float* c,
                                     unsigned a0, unsigned a1, unsigned a2, unsigned a3,
                                     unsigned b0, unsigned b1) {
    asm volatile(
        "mma.sync.aligned.m16n8k8.row.col.f32.tf32.tf32.f32 "
        "{%0,%1,%2,%3}, {%4,%5,%6,%7}, {%8,%9}, {%0,%1,%2,%3};\n"
        : "+f"(c[0]), "+f"(c[1]), "+f"(c[2]), "+f"(c[3])
        : "r"(a0), "r"(a1), "r"(a2), "r"(a3), "r"(b0), "r"(b1));
}

// ---------------------------------------------------------------------------
// GEMM1: qkv[b][s][n] = sum_c x[b][c][s] * W_proj[c][n] + b_proj[n]
// 128x128 tile, BK=16, tf32 mma. 8 warps: 4(m) x 2(n), warp tile 32x64.
// ---------------------------------------------------------------------------
#define GST 136   // smem row stride (mod 32 == 8 -> conflict-free frag LDS)

__global__ __launch_bounds__(256) void gemm_qkv_kernel(
    const float* __restrict__ x, const float* __restrict__ W,
    const float* __restrict__ bias)
{
    __shared__ unsigned As[16][GST];
    __shared__ unsigned Bs[16][GST];

    const int b  = blockIdx.z;
    const int m0 = blockIdx.x * 128;   // s tile
    const int n0 = blockIdx.y * 128;   // n tile
    const float* xb = x + (size_t)b * C_ * S_;

    const int tid    = threadIdx.x;
    const int warpId = tid >> 5;
    const int lane   = tid & 31;
    const int g = lane >> 2, q = lane & 3;
    const int wm = warpId & 3;   // 0..3
    const int wn = warpId >> 2;  // 0..1

    float acc[2][8][4];
#pragma unroll
    for (int mt = 0; mt < 2; mt++)
#pragma unroll
        for (int nt = 0; nt < 8; nt++)
#pragma unroll
            for (int r = 0; r < 4; r++) acc[mt][nt][r] = 0.f;

    for (int k0 = 0; k0 < C_; k0 += 16) {
#pragma unroll
        for (int i = 0; i < 2; i++) {
            int f  = tid + i * 256;        // 0..511 float4 slots
            int kk = f >> 5;
            int m4 = (f & 31) << 2;
            float4 av = *(const float4*)(xb + (size_t)(k0 + kk) * S_ + m0 + m4);
            *(uint4*)&As[kk][m4] = make_uint4(f2tf(av.x), f2tf(av.y), f2tf(av.z), f2tf(av.w));
            float4 bv = *(const float4*)(W + (size_t)(k0 + kk) * N3_ + n0 + m4);
            *(uint4*)&Bs[kk][m4] = make_uint4(f2tf(bv.x), f2tf(bv.y), f2tf(bv.z), f2tf(bv.w));
        }
        __syncthreads();

#pragma unroll
        for (int ks = 0; ks < 2; ks++) {
            const int kb = ks * 8;
            unsigned af[2][4];
#pragma unroll
            for (int mt = 0; mt < 2; mt++) {
                int rb = wm * 32 + mt * 16 + g;
                af[mt][0] = As[kb + q][rb];
                af[mt][1] = As[kb + q][rb + 8];
                af[mt][2] = As[kb + q + 4][rb];
                af[mt][3] = As[kb + q + 4][rb + 8];
            }
#pragma unroll
            for (int nt = 0; nt < 8; nt++) {
                int cb = wn * 64 + nt * 8 + g;
                unsigned b0 = Bs[kb + q][cb];
                unsigned b1 = Bs[kb + q + 4][cb];
#pragma unroll
                for (int mt = 0; mt < 2; mt++)
                    mma8(acc[mt][nt], af[mt][0], af[mt][1], af[mt][2], af[mt][3], b0, b1);
            }
        }
        __syncthreads();
    }

#pragma unroll
    for (int mt = 0; mt < 2; mt++) {
        int r0 = m0 + wm * 32 + mt * 16 + g;
#pragma unroll
        for (int nt = 0; nt < 8; nt++) {
            int c = n0 + wn * 64 + nt * 8 + 2 * q;
            float2 bb = *(const float2*)(bias + c);
            float* p0 = &g_qkv[((size_t)b * S_ + r0) * N3_ + c];
            float* p1 = &g_qkv[((size_t)b * S_ + r0 + 8) * N3_ + c];
            *(float2*)p0 = make_float2(acc[mt][nt][0] + bb.x, acc[mt][nt][1] + bb.y);
            *(float2*)p1 = make_float2(acc[mt][nt][2] + bb.x, acc[mt][nt][3] + bb.y);
        }
    }
}

// ---------------------------------------------------------------------------
// Attention: block = (b, h, 128-query tile). 8 warps; each warp owns 16 q-rows
// (softmax is warp-local). Flash online softmax over 16 key-tiles of 64.
// tf32 mma for QK^T and PV. Q kept in register fragments; P round-trips
// through warp-private smem to re-layout C-frag -> A-frag.
// Dyn smem (unsigned/tf32): K[64][72], V[64][72], PQ[128][72] = 73728 B.
// ---------------------------------------------------------------------------
#define AST 72

__global__ __launch_bounds__(256) void attn_kernel()
{
    extern __shared__ unsigned sm[];
    unsigned* Ksm = sm;                 // [64][AST]
    unsigned* Vsm = sm + 64 * AST;      // [64][AST]
    unsigned* Psm = sm + 128 * AST;     // [128][AST]  (Q staging, then P)

    const int b  = blockIdx.z;
    const int h  = blockIdx.y;
    const int q0 = blockIdx.x * 128;

    const int tid    = threadIdx.x;
    const int warpId = tid >> 5;
    const int lane   = tid & 31;
    const int g = lane >> 2, q = lane & 3;
    const int wbase = warpId * 16;      // warp's q-row base within tile

    const float* base = g_qkv + (size_t)b * S_ * N3_ + h * 192;

    // --- Stage Q tile (128x64) -> smem (tf32), then to register A-fragments
#pragma unroll
    for (int i = 0; i < 8; i++) {
        int f  = tid + i * 256;          // 0..2047 float4 slots
        int r  = f >> 4;
        int d4 = (f & 15) << 2;
        float4 v = *(const float4*)(base + (size_t)(q0 + r) * N3_ + d4);
        *(uint4*)&Psm[r * AST + d4] = make_uint4(f2tf(v.x), f2tf(v.y), f2tf(v.z), f2tf(v.w));
    }
    __syncthreads();

    unsigned qf[8][4];
#pragma unroll
    for (int ks = 0; ks < 8; ks++) {
        int kb = ks * 8;
        qf[ks][0] = Psm[(wbase + g) * AST + kb + q];
        qf[ks][1] = Psm[(wbase + g + 8) * AST + kb + q];
        qf[ks][2] = Psm[(wbase + g) * AST + kb + q + 4];
        qf[ks][3] = Psm[(wbase + g + 8) * AST + kb + q + 4];
    }
    __syncthreads();   // all warps done reading Q before Psm is reused for P

    float o[8][4];
#pragma unroll
    for (int nt = 0; nt < 8; nt++)
#pragma unroll
        for (int r = 0; r < 4; r++) o[nt][r] = 0.f;
    float mv[2] = {-1e30f, -1e30f};
    float lv[2] = {0.f, 0.f};

    for (int kt = 0; kt < 16; kt++) {
        __syncthreads();   // protect K/V from previous iteration readers
#pragma unroll
        for (int i = 0; i < 4; i++) {
            int f  = tid + i * 256;      // 0..1023 float4 slots
            int r  = f >> 4;
            int d4 = (f & 15) << 2;
            const float* kp = base + (size_t)(kt * 64 + r) * N3_ + 64 + d4;
            float4 kv = *(const float4*)kp;
            *(uint4*)&Ksm[r * AST + d4] = make_uint4(f2tf(kv.x), f2tf(kv.y), f2tf(kv.z), f2tf(kv.w));
            float4 vv = *(const float4*)(kp + 64);
            *(uint4*)&Vsm[r * AST + d4] = make_uint4(f2tf(vv.x), f2tf(vv.y), f2tf(vv.z), f2tf(vv.w));
        }
        __syncthreads();

        // --- S = Q @ K^T (16 x 64 per warp)
        float s[8][4];
#pragma unroll
        for (int nt = 0; nt < 8; nt++)
#pragma unroll
            for (int r = 0; r < 4; r++) s[nt][r] = 0.f;

#pragma unroll
        for (int ks = 0; ks < 8; ks++) {
            int kb = ks * 8;
#pragma unroll
            for (int nt = 0; nt < 8; nt++) {
                int key = nt * 8 + g;
                unsigned b0 = Ksm[key * AST + kb + q];
                unsigned b1 = Ksm[key * AST + kb + q + 4];
                mma8(s[nt], qf[ks][0], qf[ks][1], qf[ks][2], qf[ks][3], b0, b1);
            }
        }

        // --- Online softmax (rows are warp-local; quad-shuffle reductions)
#pragma unroll
        for (int rh = 0; rh < 2; rh++) {
            const int j0 = 2 * rh, j1 = 2 * rh + 1;
            float vmax = -1e30f;
#pragma unroll
            for (int nt = 0; nt < 8; nt++) {
                s[nt][j0] *= SCALE_;
                s[nt][j1] *= SCALE_;
                vmax = fmaxf(vmax, fmaxf(s[nt][j0], s[nt][j1]));
            }
            vmax = fmaxf(vmax, __shfl_xor_sync(0xffffffffu, vmax, 1));
            vmax = fmaxf(vmax, __shfl_xor_sync(0xffffffffu, vmax, 2));
            float mn = fmaxf(mv[rh], vmax);
            float fs = __expf(mv[rh] - mn);
            float sum = 0.f;
#pragma unroll
            for (int nt = 0; nt < 8; nt++) {
                float p0 = __expf(s[nt][j0] - mn);
                float p1 = __expf(s[nt][j1] - mn);
                s[nt][j0] = p0; s[nt][j1] = p1;
                sum += p0 + p1;
            }
            sum += __shfl_xor_sync(0xffffffffu, sum, 1);
            sum += __shfl_xor_sync(0xffffffffu, sum, 2);
            lv[rh] = lv[rh] * fs + sum;
            mv[rh] = mn;
#pragma unroll
            for (int nt = 0; nt < 8; nt++) {
                o[nt][j0] *= fs;
                o[nt][j1] *= fs;
            }
        }

        // --- P -> smem (warp-private rows) for A-fragment re-layout
#pragma unroll
        for (int nt = 0; nt < 8; nt++) {
            int col = nt * 8 + 2 * q;
            *(uint2*)&Psm[(wbase + g) * AST + col] =
                make_uint2(f2tf(s[nt][0]), f2tf(s[nt][1]));
            *(uint2*)&Psm[(wbase + g + 8) * AST + col] =
                make_uint2(f2tf(s[nt][2]), f2tf(s[nt][3]));
        }
        __syncwarp();

        // --- O += P @ V
#pragma unroll
        for (int ks = 0; ks < 8; ks++) {
            int kb = ks * 8;
            unsigned pa0 = Psm[(wbase + g) * AST + kb + q];
            unsigned pa1 = Psm[(wbase + g + 8) * AST + kb + q];
            unsigned pa2 = Psm[(wbase + g) * AST + kb + q + 4];
            unsigned pa3 = Psm[(wbase + g + 8) * AST + kb + q + 4];
#pragma unroll
            for (int nt = 0; nt < 8; nt++) {
                int col = nt * 8 + g;
                unsigned b0 = Vsm[(kb + q) * AST + col];
                unsigned b1 = Vsm[(kb + q + 4) * AST + col];
                mma8(o[nt], pa0, pa1, pa2, pa3, b0, b1);
            }
        }
        __syncwarp();   // PV reads done before next iteration's P stores
    }

    // --- Epilogue: normalize and write res[b][q][h*64 + d]
    float inv0 = 1.f / lv[0];
    float inv1 = 1.f / lv[1];
    int r0 = q0 + wbase + g;
#pragma unroll
    for (int nt = 0; nt < 8; nt++) {
        int col = h * 64 + nt * 8 + 2 * q;
        float* p0 = &g_res[((size_t)b * S_ + r0) * INNER_ + col];
        float* p1 = &g_res[((size_t)b * S_ + r0 + 8) * INNER_ + col];
        *(float2*)p0 = make_float2(o[nt][0] * inv0, o[nt][1] * inv0);
        *(float2*)p1 = make_float2(o[nt][2] * inv1, o[nt][3] * inv1);
    }
}

// ---------------------------------------------------------------------------
// GEMM3: out[b][c][s] = sum_k res[b][s][k] * W_out[k][c] + b_out[c] + x[b][c][s]
// M = c (rows, from W_out columns), N = s. tf32 mma, same tiling as GEMM1.
// ---------------------------------------------------------------------------
__global__ __launch_bounds__(256) void gemm_out_kernel(
    const float* __restrict__ Wo, const float* __restrict__ bo,
    const float* __restrict__ x, float* __restrict__ out)
{
    __shared__ unsigned As[16][GST];
    __shared__ unsigned Bs[16][GST];

    const int b  = blockIdx.z;
    const int c0 = blockIdx.x * 128;   // c tile (M)
    const int s0 = blockIdx.y * 128;   // s tile (N)

    const int tid    = threadIdx.x;
    const int warpId = tid >> 5;
    const int lane   = tid & 31;
    const int g = lane >> 2, q = lane & 3;
    const int wm = warpId & 3;
    const int wn = warpId >> 2;

    const float* resb = g_res + (size_t)b * S_ * INNER_;

    float acc[2][8][4];
#pragma unroll
    for (int mt = 0; mt < 2; mt++)
#pragma unroll
        for (int nt = 0; nt < 8; nt++)
#pragma unroll
            for (int r = 0; r < 4; r++) acc[mt][nt][r] = 0.f;

    for (int k0 = 0; k0 < INNER_; k0 += 16) {
        // A[m=c][k] = Wo[k][c]   (coalesced along c)
#pragma unroll
        for (int i = 0; i < 2; i++) {
            int f  = tid + i * 256;
            int kk = f >> 5;
            int m4 = (f & 31) << 2;
            float4 av = *(const float4*)(Wo + (size_t)(k0 + kk) * C_ + c0 + m4);
            *(uint4*)&As[kk][m4] = make_uint4(f2tf(av.x), f2tf(av.y), f2tf(av.z), f2tf(av.w));
        }
        // B[k][n=s] = res[s][k]  (vectorized along k)
#pragma unroll
        for (int i = 0; i < 2; i++) {
            int f  = tid + i * 256;       // 0..511
            int nn = f >> 2;              // 0..127
            int kq = f & 3;               // 4 float4 per row of 16 k
            float4 rv = *(const float4*)(resb + (size_t)(s0 + nn) * INNER_ + k0 + kq * 4);
            Bs[kq * 4 + 0][nn] = f2tf(rv.x);
            Bs[kq * 4 + 1][nn] = f2tf(rv.y);
            Bs[kq * 4 + 2][nn] = f2tf(rv.z);
            Bs[kq * 4 + 3][nn] = f2tf(rv.w);
        }
        __syncthreads();

#pragma unroll
        for (int ks = 0; ks < 2; ks++) {
            const int kb = ks * 8;
            unsigned af[2][4];
#pragma unroll
            for (int mt = 0; mt < 2; mt++) {
                int rb = wm * 32 + mt * 16 + g;
                af[mt][0] = As[kb + q][rb];
                af[mt][1] = As[kb + q][rb + 8];
                af[mt][2] = As[kb + q + 4][rb];
                af[mt][3] = As[kb + q + 4][rb + 8];
            }
#pragma unroll
            for (int nt = 0; nt < 8; nt++) {
                int cb = wn * 64 + nt * 8 + g;
                unsigned b0 = Bs[kb + q][cb];
                unsigned b1 = Bs[kb + q + 4][cb];
#pragma unroll
                for (int mt = 0; mt < 2; mt++)
                    mma8(acc[mt][nt], af[mt][0], af[mt][1], af[mt][2], af[mt][3], b0, b1);
            }
        }
        __syncthreads();
    }

    const float* xb = x + (size_t)b * C_ * S_;
    float* ob = out + (size_t)b * C_ * S_;
#pragma unroll
    for (int mt = 0; mt < 2; mt++) {
        int cc0 = c0 + wm * 32 + mt * 16 + g;
#pragma unroll
        for (int nt = 0; nt < 8; nt++) {
            int ss = s0 + wn * 64 + nt * 8 + 2 * q;
            float bias0 = __ldg(bo + cc0);
            float bias1 = __ldg(bo + cc0 + 8);
            float2 x0 = *(const float2*)(xb + (size_t)cc0 * S_ + ss);
            float2 x1 = *(const float2*)(xb + (size_t)(cc0 + 8) * S_ + ss);
            *(float2*)(ob + (size_t)cc0 * S_ + ss) =
                make_float2(acc[mt][nt][0] + bias0 + x0.x, acc[mt][nt][1] + bias0 + x0.y);
            *(float2*)(ob + (size_t)(cc0 + 8) * S_ + ss) =
                make_float2(acc[mt][nt][2] + bias1 + x1.x, acc[mt][nt][3] + bias1 + x1.y);
        }
    }
}

// ---------------------------------------------------------------------------
extern "C" void kernel_launch(void* const* d_in, const int* in_sizes, int n_in,
                              void* d_out, int out_size)
{
    const float* x  = (const float*)d_in[0];
    const float* Wp = (const float*)d_in[1];
    const float* bp = (const float*)d_in[2];
    const float* Wo = (const float*)d_in[3];
    const float* bo = (const float*)d_in[4];
    float* out = (float*)d_out;

    static const int attn_smem = (64 + 64 + 128) * AST * (int)sizeof(unsigned); // 73728
    cudaFuncSetAttribute(attn_kernel, cudaFuncAttributeMaxDynamicSharedMemorySize, attn_smem);

    // Stage 1: QKV projection (tf32 tensor)
    gemm_qkv_kernel<<<dim3(S_ / 128, N3_ / 128, B_), 256>>>(x, Wp, bp);

    // Stage 2: fused flash attention (tf32 tensor)
    attn_kernel<<<dim3(S_ / 128, H_, B_), 256, attn_smem>>>();

    // Stage 3: output projection + bias + residual + transpose (tf32 tensor)
    gemm_out_kernel<<<dim3(C_ / 128, S_ / 128, B_), 256>>>(Wo, bo, x, out);
}

// round 4
// speedup vs baseline: 3.8766x; 1.2071x over previous
#include <cuda_runtime.h>

#define B_     16
#define C_     512
#define S_     1024
#define H_     8
#define DH_    64
#define N3_    1536
#define INNER_ 512
#define SCALE_ 0.125f

// Scratch (allocation-free rule: __device__ globals)
__device__ float g_qkv[(size_t)B_ * S_ * N3_];    // (b, s, 1536) — tf32-rounded
__device__ float g_res[(size_t)B_ * S_ * INNER_]; // (b, s, 512)  — tf32-rounded
__device__ float g_xr[(size_t)B_ * C_ * S_];      // x rounded to tf32
__device__ float g_wpr[(size_t)C_ * N3_];         // W_proj rounded
__device__ float g_wor[(size_t)INNER_ * C_];      // W_out rounded

// ---------------------------------------------------------------------------
// helpers
// ---------------------------------------------------------------------------
__device__ __forceinline__ unsigned f2tf(float f) {
    unsigned u;
    asm("cvt.rna.tf32.f32 %0, %1;" : "=r"(u) : "f"(f));
    return u;
}
__device__ __forceinline__ float rtf(float f) { return __uint_as_float(f2tf(f)); }

// D += A(16x8, row) * B(8x8, col)  tf32 -> f32 (inputs are exact tf32 values)
__device__ __forceinline__ void mma8(float* c,
                                     unsigned a0, unsigned a1, unsigned a2, unsigned a3,
                                     unsigned b0, unsigned b1) {
    asm volatile(
        "mma.sync.aligned.m16n8k8.row.col.f32.tf32.tf32.f32 "
        "{%0,%1,%2,%3}, {%4,%5,%6,%7}, {%8,%9}, {%0,%1,%2,%3};\n"
        : "+f"(c[0]), "+f"(c[1]), "+f"(c[2]), "+f"(c[3])
        : "r"(a0), "r"(a1), "r"(a2), "r"(a3), "r"(b0), "r"(b1));
}

__device__ __forceinline__ void cpa16(void* dst, const void* src) {
    unsigned d = (unsigned)__cvta_generic_to_shared(dst);
    asm volatile("cp.async.cg.shared.global [%0], [%1], 16;\n" :: "r"(d), "l"(src));
}
__device__ __forceinline__ void cp_commit() {
    asm volatile("cp.async.commit_group;\n");
}
template <int N> __device__ __forceinline__ void cp_wait() {
    asm volatile("cp.async.wait_group %0;\n" :: "n"(N));
}

// ---------------------------------------------------------------------------
// Prep: round arrays to tf32 (round-to-nearest) so GEMM inputs are exact tf32
// ---------------------------------------------------------------------------
__global__ __launch_bounds__(256) void round_tf32_kernel(
    const float4* __restrict__ in, float4* __restrict__ out, int n4)
{
    int i = blockIdx.x * blockDim.x + threadIdx.x;
    if (i < n4) {
        float4 v = in[i];
        out[i] = make_float4(rtf(v.x), rtf(v.y), rtf(v.z), rtf(v.w));
    }
}

// ---------------------------------------------------------------------------
// GEMM1: qkv[b][s][n] = sum_c x[b][c][s] * W_proj[c][n] + b_proj[n]
// Block 128(m) x 256(n) x BK=16. 8 warps = 2(m) x 4(n); warp tile 64x64.
// cp.async 2-stage double buffer. Strides ==8 mod 32 -> conflict-free frags.
// ---------------------------------------------------------------------------
#define STA 136
#define STB 264
#define A_STAGE (16 * STA)
#define B_STAGE (16 * STB)
#define G1_SMEM ((2 * A_STAGE + 2 * B_STAGE) * 4)

__global__ __launch_bounds__(256) void gemm_qkv_kernel(
    const float* __restrict__ x, const float* __restrict__ W,
    const float* __restrict__ bias)
{
    extern __shared__ unsigned dsm[];

    const int b  = blockIdx.z;
    const int m0 = blockIdx.x * 128;   // s tile
    const int n0 = blockIdx.y * 256;   // n tile
    const float* xb = x + (size_t)b * C_ * S_;

    const int tid    = threadIdx.x;
    const int warpId = tid >> 5;
    const int lane   = tid & 31;
    const int g = lane >> 2, q = lane & 3;
    const int wm = warpId & 1;    // 0..1
    const int wn = warpId >> 1;   // 0..3

    float acc[4][8][4];
#pragma unroll
    for (int mt = 0; mt < 4; mt++)
#pragma unroll
        for (int nt = 0; nt < 8; nt++)
#pragma unroll
            for (int r = 0; r < 4; r++) acc[mt][nt][r] = 0.f;

    auto load_tiles = [&](int k0, int p) {
        unsigned* A  = dsm + p * A_STAGE;
        unsigned* Bv = dsm + 2 * A_STAGE + p * B_STAGE;
#pragma unroll
        for (int i = 0; i < 2; i++) {
            int f = tid + i * 256;          // 512 float4 slots (16x128)
            int kk = f >> 5, m4 = (f & 31) << 2;
            cpa16(&A[kk * STA + m4], xb + (size_t)(k0 + kk) * S_ + m0 + m4);
        }
#pragma unroll
        for (int i = 0; i < 4; i++) {
            int f = tid + i * 256;          // 1024 float4 slots (16x256)
            int kk = f >> 6, n4 = (f & 63) << 2;
            cpa16(&Bv[kk * STB + n4], W + (size_t)(k0 + kk) * N3_ + n0 + n4);
        }
    };

    load_tiles(0, 0);  cp_commit();
    load_tiles(16, 1); cp_commit();

    const int T = C_ / 16;   // 32
    for (int t = 0; t < T; t++) {
        if (t < T - 1) cp_wait<1>(); else cp_wait<0>();
        __syncthreads();

        const int p = t & 1;
        const unsigned* A  = dsm + p * A_STAGE;
        const unsigned* Bv = dsm + 2 * A_STAGE + p * B_STAGE;

#pragma unroll
        for (int ks = 0; ks < 2; ks++) {
            const int kb = ks * 8;
            unsigned af[4][4];
#pragma unroll
            for (int mt = 0; mt < 4; mt++) {
                int rb = wm * 64 + mt * 16 + g;
                af[mt][0] = A[(kb + q) * STA + rb];
                af[mt][1] = A[(kb + q) * STA + rb + 8];
                af[mt][2] = A[(kb + q + 4) * STA + rb];
                af[mt][3] = A[(kb + q + 4) * STA + rb + 8];
            }
#pragma unroll
            for (int nt = 0; nt < 8; nt++) {
                int cb = wn * 64 + nt * 8 + g;
                unsigned b0 = Bv[(kb + q) * STB + cb];
                unsigned b1 = Bv[(kb + q + 4) * STB + cb];
#pragma unroll
                for (int mt = 0; mt < 4; mt++)
                    mma8(acc[mt][nt], af[mt][0], af[mt][1], af[mt][2], af[mt][3], b0, b1);
            }
        }
        __syncthreads();
        if (t + 2 < T) { load_tiles((t + 2) * 16, p); cp_commit(); }
    }

    // Epilogue: add bias, round to tf32 (downstream consumers feed MMA raw)
#pragma unroll
    for (int mt = 0; mt < 4; mt++) {
        int r0 = m0 + wm * 64 + mt * 16 + g;
#pragma unroll
        for (int nt = 0; nt < 8; nt++) {
            int c = n0 + wn * 64 + nt * 8 + 2 * q;
            float2 bb = *(const float2*)(bias + c);
            float* p0 = &g_qkv[((size_t)b * S_ + r0) * N3_ + c];
            float* p1 = &g_qkv[((size_t)b * S_ + r0 + 8) * N3_ + c];
            *(float2*)p0 = make_float2(rtf(acc[mt][nt][0] + bb.x), rtf(acc[mt][nt][1] + bb.y));
            *(float2*)p1 = make_float2(rtf(acc[mt][nt][2] + bb.x), rtf(acc[mt][nt][3] + bb.y));
        }
    }
}

// ---------------------------------------------------------------------------
// Attention: block = (b, h, 128-query tile). 8 warps x 16 q-rows each.
// Flash online softmax, 16 key-tiles of 64, cp.async double-buffered K/V.
// Strides: K/P 76 (g-row pattern conflict-free), V 72 (q-row pattern cf).
// ---------------------------------------------------------------------------
#define STK 76
#define STV 72
#define K_STAGE (64 * STK)
#define V_STAGE (64 * STV)
#define ATT_SMEM ((2 * K_STAGE + 2 * V_STAGE + 128 * STK) * 4)

__global__ __launch_bounds__(256) void attn_kernel()
{
    extern __shared__ unsigned sm[];
    unsigned* Psm = sm + 2 * K_STAGE + 2 * V_STAGE;   // [128][STK]

    const int b  = blockIdx.z;
    const int h  = blockIdx.y;
    const int q0 = blockIdx.x * 128;

    const int tid    = threadIdx.x;
    const int warpId = tid >> 5;
    const int lane   = tid & 31;
    const int g = lane >> 2, q = lane & 3;
    const int wbase = warpId * 16;

    const float* base = g_qkv + (size_t)b * S_ * N3_ + h * 192;

    auto load_kv = [&](int kt, int p) {
        unsigned* K = sm + p * K_STAGE;
        unsigned* V = sm + 2 * K_STAGE + p * V_STAGE;
#pragma unroll
        for (int i = 0; i < 4; i++) {
            int f = tid + i * 256;          // 1024 float4 slots (64 rows x 16)
            int r = f >> 4, c4 = (f & 15) << 2;
            const float* kp = base + (size_t)(kt * 64 + r) * N3_ + 64 + c4;
            cpa16(&K[r * STK + c4], kp);
            cpa16(&V[r * STV + c4], kp + 64);
        }
    };

    // Q tile -> Psm (group 0), then prefetch kt=0,1
#pragma unroll
    for (int i = 0; i < 8; i++) {
        int f = tid + i * 256;            // 2048 float4 slots (128x64)
        int r = f >> 4, c4 = (f & 15) << 2;
        cpa16(&Psm[r * STK + c4], base + (size_t)(q0 + r) * N3_ + c4);
    }
    cp_commit();
    load_kv(0, 0); cp_commit();
    load_kv(1, 1); cp_commit();

    cp_wait<2>();        // Q ready
    __syncthreads();

    unsigned qf[8][4];
#pragma unroll
    for (int ks = 0; ks < 8; ks++) {
        int kb = ks * 8;
        qf[ks][0] = Psm[(wbase + g) * STK + kb + q];
        qf[ks][1] = Psm[(wbase + g + 8) * STK + kb + q];
        qf[ks][2] = Psm[(wbase + g) * STK + kb + q + 4];
        qf[ks][3] = Psm[(wbase + g + 8) * STK + kb + q + 4];
    }
    __syncthreads();     // Q reads done before Psm reused for P

    float o[8][4];
#pragma unroll
    for (int nt = 0; nt < 8; nt++)
#pragma unroll
        for (int r = 0; r < 4; r++) o[nt][r] = 0.f;
    float mv[2] = {-1e30f, -1e30f};
    float lv[2] = {0.f, 0.f};

    for (int kt = 0; kt < 16; kt++) {
        if (kt < 15) cp_wait<1>(); else cp_wait<0>();
        __syncthreads();

        const int p = kt & 1;
        const unsigned* Ksm = sm + p * K_STAGE;
        const unsigned* Vsm = sm + 2 * K_STAGE + p * V_STAGE;

        // --- S = Q @ K^T (16 x 64 per warp)
        float s[8][4];
#pragma unroll
        for (int nt = 0; nt < 8; nt++)
#pragma unroll
            for (int r = 0; r < 4; r++) s[nt][r] = 0.f;

#pragma unroll
        for (int ks = 0; ks < 8; ks++) {
            int kb = ks * 8;
#pragma unroll
            for (int nt = 0; nt < 8; nt++) {
                int key = nt * 8 + g;
                unsigned b0 = Ksm[key * STK + kb + q];
                unsigned b1 = Ksm[key * STK + kb + q + 4];
                mma8(s[nt], qf[ks][0], qf[ks][1], qf[ks][2], qf[ks][3], b0, b1);
            }
        }

        // --- Online softmax (warp-local rows; quad shuffles)
#pragma unroll
        for (int rh = 0; rh < 2; rh++) {
            const int j0 = 2 * rh, j1 = 2 * rh + 1;
            float vmax = -1e30f;
#pragma unroll
            for (int nt = 0; nt < 8; nt++) {
                s[nt][j0] *= SCALE_;
                s[nt][j1] *= SCALE_;
                vmax = fmaxf(vmax, fmaxf(s[nt][j0], s[nt][j1]));
            }
            vmax = fmaxf(vmax, __shfl_xor_sync(0xffffffffu, vmax, 1));
            vmax = fmaxf(vmax, __shfl_xor_sync(0xffffffffu, vmax, 2));
            float mn = fmaxf(mv[rh], vmax);
            float fs = __expf(mv[rh] - mn);
            float sum = 0.f;
#pragma unroll
            for (int nt = 0; nt < 8; nt++) {
                float p0 = __expf(s[nt][j0] - mn);
                float p1 = __expf(s[nt][j1] - mn);
                s[nt][j0] = p0; s[nt][j1] = p1;
                sum += p0 + p1;
            }
            sum += __shfl_xor_sync(0xffffffffu, sum, 1);
            sum += __shfl_xor_sync(0xffffffffu, sum, 2);
            lv[rh] = lv[rh] * fs + sum;
            mv[rh] = mn;
#pragma unroll
            for (int nt = 0; nt < 8; nt++) {
                o[nt][j0] *= fs;
                o[nt][j1] *= fs;
            }
        }

        // --- P -> smem (warp-private rows), rounded to tf32
#pragma unroll
        for (int nt = 0; nt < 8; nt++) {
            int col = nt * 8 + 2 * q;
            *(uint2*)&Psm[(wbase + g) * STK + col] =
                make_uint2(f2tf(s[nt][0]), f2tf(s[nt][1]));
            *(uint2*)&Psm[(wbase + g + 8) * STK + col] =
                make_uint2(f2tf(s[nt][2]), f2tf(s[nt][3]));
        }
        __syncwarp();

        // --- O += P @ V
#pragma unroll
        for (int ks = 0; ks < 8; ks++) {
            int kb = ks * 8;
            unsigned pa0 = Psm[(wbase + g) * STK + kb + q];
            unsigned pa1 = Psm[(wbase + g + 8) * STK + kb + q];
            unsigned pa2 = Psm[(wbase + g) * STK + kb + q + 4];
            unsigned pa3 = Psm[(wbase + g + 8) * STK + kb + q + 4];
#pragma unroll
            for (int nt = 0; nt < 8; nt++) {
                int col = nt * 8 + g;
                unsigned b0 = Vsm[(kb + q) * STV + col];
                unsigned b1 = Vsm[(kb + q + 4) * STV + col];
                mma8(o[nt], pa0, pa1, pa2, pa3, b0, b1);
            }
        }
        __syncthreads();   // all reads of stage p done before refill
        if (kt + 2 < 16) { load_kv(kt + 2, p); cp_commit(); }
    }

    // --- Epilogue: normalize, round to tf32, write res[b][q][h*64 + d]
    float inv0 = 1.f / lv[0];
    float inv1 = 1.f / lv[1];
    int r0 = q0 + wbase + g;
#pragma unroll
    for (int nt = 0; nt < 8; nt++) {
        int col = h * 64 + nt * 8 + 2 * q;
        float* p0 = &g_res[((size_t)b * S_ + r0) * INNER_ + col];
        float* p1 = &g_res[((size_t)b * S_ + r0 + 8) * INNER_ + col];
        *(float2*)p0 = make_float2(rtf(o[nt][0] * inv0), rtf(o[nt][1] * inv0));
        *(float2*)p1 = make_float2(rtf(o[nt][2] * inv1), rtf(o[nt][3] * inv1));
    }
}

// ---------------------------------------------------------------------------
// GEMM3: out[b][c][s] = sum_k res[b][s][k] * W_out[k][c] + b_out[c] + x[b][c][s]
// Block 128(c) x 256(s) x BK=16, same warp layout as GEMM1.
// B tile stored n-major [256][20] so the transposed res load stays 16B.
// ---------------------------------------------------------------------------
#define STB3 20
#define B3_STAGE (256 * STB3)
#define G3_SMEM ((2 * A_STAGE + 2 * B3_STAGE) * 4)

__global__ __launch_bounds__(256) void gemm_out_kernel(
    const float* __restrict__ Wo, const float* __restrict__ bo,
    const float* __restrict__ x, float* __restrict__ out)
{
    extern __shared__ unsigned dsm[];

    const int b  = blockIdx.z;
    const int c0 = blockIdx.x * 128;   // c tile (M)
    const int s0 = blockIdx.y * 256;   // s tile (N)

    const int tid    = threadIdx.x;
    const int warpId = tid >> 5;
    const int lane   = tid & 31;
    const int g = lane >> 2, q = lane & 3;
    const int wm = warpId & 1;
    const int wn = warpId >> 1;

    const float* resb = g_res + (size_t)b * S_ * INNER_;

    float acc[4][8][4];
#pragma unroll
    for (int mt = 0; mt < 4; mt++)
#pragma unroll
        for (int nt = 0; nt < 8; nt++)
#pragma unroll
            for (int r = 0; r < 4; r++) acc[mt][nt][r] = 0.f;

    auto load_tiles = [&](int k0, int p) {
        unsigned* A  = dsm + p * A_STAGE;
        unsigned* Bn = dsm + 2 * A_STAGE + p * B3_STAGE;
#pragma unroll
        for (int i = 0; i < 2; i++) {
            int f = tid + i * 256;            // 16 x 128 A tile
            int kk = f >> 5, m4 = (f & 31) << 2;
            cpa16(&A[kk * STA + m4], Wo + (size_t)(k0 + kk) * C_ + c0 + m4);
        }
#pragma unroll
        for (int i = 0; i < 4; i++) {
            int f = tid + i * 256;            // 256 rows x 4 float4 (k)
            int nn = f >> 2, kq = (f & 3) << 2;
            cpa16(&Bn[nn * STB3 + kq], resb + (size_t)(s0 + nn) * INNER_ + k0 + kq);
        }
    };

    load_tiles(0, 0);  cp_commit();
    load_tiles(16, 1); cp_commit();

    const int T = INNER_ / 16;   // 32
    for (int t = 0; t < T; t++) {
        if (t < T - 1) cp_wait<1>(); else cp_wait<0>();
        __syncthreads();

        const int p = t & 1;
        const unsigned* A  = dsm + p * A_STAGE;
        const unsigned* Bn = dsm + 2 * A_STAGE + p * B3_STAGE;

#pragma unroll
        for (int ks = 0; ks < 2; ks++) {
            const int kb = ks * 8;
            unsigned af[4][4];
#pragma unroll
            for (int mt = 0; mt < 4; mt++) {
                int rb = wm * 64 + mt * 16 + g;
                af[mt][0] = A[(kb + q) * STA + rb];
                af[mt][1] = A[(kb + q) * STA + rb + 8];
                af[mt][2] = A[(kb + q + 4) * STA + rb];
                af[mt][3] = A[(kb + q + 4) * STA + rb + 8];
            }
#pragma unroll
            for (int nt = 0; nt < 8; nt++) {
                int cb = wn * 64 + nt * 8 + g;
                unsigned b0 = Bn[cb * STB3 + kb + q];
                unsigned b1 = Bn[cb * STB3 + kb + q + 4];
#pragma unroll
                for (int mt = 0; mt < 4; mt++)
                    mma8(acc[mt][nt], af[mt][0], af[mt][1], af[mt][2], af[mt][3], b0, b1);
            }
        }
        __syncthreads();
        if (t + 2 < T) { load_tiles((t + 2) * 16, p); cp_commit(); }
    }

    const float* xb = x + (size_t)b * C_ * S_;
    float* ob = out + (size_t)b * C_ * S_;
#pragma unroll
    for (int mt = 0; mt < 4; mt++) {
        int cc0 = c0 + wm * 64 + mt * 16 + g;
        float bias0 = __ldg(bo + cc0);
        float bias1 = __ldg(bo + cc0 + 8);
#pragma unroll
        for (int nt = 0; nt < 8; nt++) {
            int ss = s0 + wn * 64 + nt * 8 + 2 * q;
            float2 x0 = *(const float2*)(xb + (size_t)cc0 * S_ + ss);
            float2 x1 = *(const float2*)(xb + (size_t)(cc0 + 8) * S_ + ss);
            *(float2*)(ob + (size_t)cc0 * S_ + ss) =
                make_float2(acc[mt][nt][0] + bias0 + x0.x, acc[mt][nt][1] + bias0 + x0.y);
            *(float2*)(ob + (size_t)(cc0 + 8) * S_ + ss) =
                make_float2(acc[mt][nt][2] + bias1 + x1.x, acc[mt][nt][3] + bias1 + x1.y);
        }
    }
}

// ---------------------------------------------------------------------------
extern "C" void kernel_launch(void* const* d_in, const int* in_sizes, int n_in,
                              void* d_out, int out_size)
{
    const float* x  = (const float*)d_in[0];
    const float* Wp = (const float*)d_in[1];
    const float* bp = (const float*)d_in[2];
    const float* Wo = (const float*)d_in[3];
    const float* bo = (const float*)d_in[4];
    float* out = (float*)d_out;

    cudaFuncSetAttribute(gemm_qkv_kernel, cudaFuncAttributeMaxDynamicSharedMemorySize, G1_SMEM);
    cudaFuncSetAttribute(attn_kernel,     cudaFuncAttributeMaxDynamicSharedMemorySize, ATT_SMEM);
    cudaFuncSetAttribute(gemm_out_kernel, cudaFuncAttributeMaxDynamicSharedMemorySize, G3_SMEM);

    float *xr, *wpr, *wor;
    cudaGetSymbolAddress((void**)&xr,  g_xr);
    cudaGetSymbolAddress((void**)&wpr, g_wpr);
    cudaGetSymbolAddress((void**)&wor, g_wor);

    // Stage 0: round inputs to exact tf32 values
    const int nx  = B_ * C_ * S_ / 4;     // 2,097,152
    const int nwp = C_ * N3_ / 4;         // 196,608
    const int nwo = INNER_ * C_ / 4;      // 65,536
    round_tf32_kernel<<<(nx  + 255) / 256, 256>>>((const float4*)x,  (float4*)xr,  nx);
    round_tf32_kernel<<<(nwp + 255) / 256, 256>>>((const float4*)Wp, (float4*)wpr, nwp);
    round_tf32_kernel<<<(nwo + 255) / 256, 256>>>((const float4*)Wo, (float4*)wor, nwo);

    // Stage 1: QKV projection
    gemm_qkv_kernel<<<dim3(S_ / 128, N3_ / 256, B_), 256, G1_SMEM>>>(xr, wpr, bp);

    // Stage 2: fused flash attention
    attn_kernel<<<dim3(S_ / 128, H_, B_), 256, ATT_SMEM>>>();

    // Stage 3: output projection + bias + residual + transpose
    gemm_out_kernel<<<dim3(C_ / 128, S_ / 256, B_), 256, G3_SMEM>>>(wor, bo, x, out);
}

// round 5
// speedup vs baseline: 6.5537x; 1.6906x over previous
#include <cuda_runtime.h>
#include <cstdint>

#define B_     16
#define C_     512
#define S_     1024
#define H_     8
#define DH_    64
#define N3_    1536
#define INNER_ 512
#define SCALE_ 0.125f

// bf16 scratch (allocation-free rule: __device__ globals)
__device__ uint16_t g_xb [(size_t)B_ * C_ * S_];    // x  -> bf16 (b,c,s)
__device__ uint16_t g_wpb[(size_t)C_ * N3_];        // W_proj bf16
__device__ uint16_t g_wob[(size_t)INNER_ * C_];     // W_out bf16
__device__ uint16_t g_qkvb[(size_t)B_ * S_ * N3_];  // qkv bf16 (b,s,1536)
__device__ uint16_t g_resb[(size_t)B_ * S_ * INNER_]; // attn out bf16 (b,s,512)

// ---------------------------------------------------------------------------
// helpers
// ---------------------------------------------------------------------------
__device__ __forceinline__ unsigned pk(float lo, float hi) {  // bf16x2(lo,hi)
    unsigned r;
    asm("cvt.rn.bf16x2.f32 %0, %1, %2;" : "=r"(r) : "f"(hi), "f"(lo));
    return r;
}

// D += A(16x16) * B(16x8)  bf16 -> f32
__device__ __forceinline__ void mma16(float* c,
                                      unsigned a0, unsigned a1, unsigned a2, unsigned a3,
                                      unsigned b0, unsigned b1) {
    asm volatile(
        "mma.sync.aligned.m16n8k16.row.col.f32.bf16.bf16.f32 "
        "{%0,%1,%2,%3}, {%4,%5,%6,%7}, {%8,%9}, {%0,%1,%2,%3};\n"
        : "+f"(c[0]), "+f"(c[1]), "+f"(c[2]), "+f"(c[3])
        : "r"(a0), "r"(a1), "r"(a2), "r"(a3), "r"(b0), "r"(b1));
}

__device__ __forceinline__ void ldsm4(unsigned& r0, unsigned& r1, unsigned& r2, unsigned& r3,
                                      const uint16_t* p) {
    unsigned a = (unsigned)__cvta_generic_to_shared(p);
    asm volatile("ldmatrix.sync.aligned.m8n8.x4.shared.b16 {%0,%1,%2,%3}, [%4];\n"
                 : "=r"(r0), "=r"(r1), "=r"(r2), "=r"(r3) : "r"(a));
}
__device__ __forceinline__ void ldsm4t(unsigned& r0, unsigned& r1, unsigned& r2, unsigned& r3,
                                       const uint16_t* p) {
    unsigned a = (unsigned)__cvta_generic_to_shared(p);
    asm volatile("ldmatrix.sync.aligned.m8n8.x4.trans.shared.b16 {%0,%1,%2,%3}, [%4];\n"
                 : "=r"(r0), "=r"(r1), "=r"(r2), "=r"(r3) : "r"(a));
}

__device__ __forceinline__ void cpa16(void* dst, const void* src) {
    unsigned d = (unsigned)__cvta_generic_to_shared(dst);
    asm volatile("cp.async.cg.shared.global [%0], [%1], 16;\n" :: "r"(d), "l"(src));
}
__device__ __forceinline__ void cp_commit() { asm volatile("cp.async.commit_group;\n"); }
template <int N> __device__ __forceinline__ void cp_wait() {
    asm volatile("cp.async.wait_group %0;\n" :: "n"(N));
}

// ---------------------------------------------------------------------------
// Prep: fp32 -> bf16 (round-to-nearest)
// ---------------------------------------------------------------------------
__global__ __launch_bounds__(256) void to_bf16_kernel(
    const float4* __restrict__ in, uint2* __restrict__ out, int n4)
{
    int i = blockIdx.x * blockDim.x + threadIdx.x;
    if (i < n4) {
        float4 v = in[i];
        out[i] = make_uint2(pk(v.x, v.y), pk(v.z, v.w));
    }
}

// ---------------------------------------------------------------------------
// GEMM1: qkv[b][s][n] = sum_c x[b][c][s] * W_proj[c][n] + b_proj[n]   (bf16 MMA)
// Block 128(m) x 256(n) x BK=32. 8 warps = 2(m) x 4(n); warp tile 64x64.
// 3-stage cp.async pipeline. Strides: A 136, B 264 elems (272B/528B, ==16 mod
// 128 -> ldmatrix 8-row groups conflict-free).
// ---------------------------------------------------------------------------
#define STA  136
#define STB1 264
#define A_ST (32 * STA)
#define B_ST (32 * STB1)
#define G1_SMEM (3 * (A_ST + B_ST) * 2)

__global__ __launch_bounds__(256) void gemm_qkv_kernel(
    const uint16_t* __restrict__ x, const uint16_t* __restrict__ W,
    const float* __restrict__ bias)
{
    extern __shared__ uint16_t sm16[];

    const int b  = blockIdx.z;
    const int m0 = blockIdx.x * 128;
    const int n0 = blockIdx.y * 256;
    const uint16_t* xb = x + (size_t)b * C_ * S_;

    const int tid = threadIdx.x, lane = tid & 31, warpId = tid >> 5;
    const int g = lane >> 2, q = lane & 3;
    const int wm = warpId & 1, wn = warpId >> 1;

    // ldmatrix lane constants
    const int ra = (lane & 7) + 8 * (lane >> 4);         // A-trans row(k)
    const int ca = 8 * ((lane >> 3) & 1);                // A-trans col(m)
    const int rk = (lane & 7) + 8 * ((lane >> 3) & 1);   // B-trans row(k)
    const int ck = 8 * (lane >> 4);                      // B-trans col(n)

    float acc[4][8][4];
#pragma unroll
    for (int mt = 0; mt < 4; mt++)
#pragma unroll
        for (int nt = 0; nt < 8; nt++)
#pragma unroll
            for (int r = 0; r < 4; r++) acc[mt][nt][r] = 0.f;

    auto load_tiles = [&](int k0, int p) {
        uint16_t* A  = sm16 + p * (A_ST + B_ST);
        uint16_t* Bv = A + A_ST;
#pragma unroll
        for (int i = 0; i < 2; i++) {
            int f = tid + i * 256;            // 512 chunks: 32 x 16
            int kk = f >> 4, m8 = (f & 15) << 3;
            cpa16(&A[kk * STA + m8], xb + (size_t)(k0 + kk) * S_ + m0 + m8);
        }
#pragma unroll
        for (int i = 0; i < 4; i++) {
            int f = tid + i * 256;            // 1024 chunks: 32 x 32
            int kk = f >> 5, n8 = (f & 31) << 3;
            cpa16(&Bv[kk * STB1 + n8], W + (size_t)(k0 + kk) * N3_ + n0 + n8);
        }
    };

    load_tiles(0, 0);  cp_commit();
    load_tiles(32, 1); cp_commit();
    load_tiles(64, 2); cp_commit();

    const int T = C_ / 32;   // 16
    for (int t = 0; t < T; t++) {
        if (t + 2 < T) cp_wait<2>(); else if (t + 1 < T) cp_wait<1>(); else cp_wait<0>();
        __syncthreads();

        const int p = t % 3;
        const uint16_t* A  = sm16 + p * (A_ST + B_ST);
        const uint16_t* Bv = A + A_ST;

#pragma unroll
        for (int ks = 0; ks < 32; ks += 16) {
            unsigned af[4][4];
#pragma unroll
            for (int mt = 0; mt < 4; mt++)
                ldsm4t(af[mt][0], af[mt][1], af[mt][2], af[mt][3],
                       &A[(ks + ra) * STA + wm * 64 + mt * 16 + ca]);
#pragma unroll
            for (int ntp = 0; ntp < 4; ntp++) {
                unsigned b0a, b1a, b0b, b1b;
                ldsm4t(b0a, b1a, b0b, b1b,
                       &Bv[(ks + rk) * STB1 + wn * 64 + ntp * 16 + ck]);
#pragma unroll
                for (int mt = 0; mt < 4; mt++) {
                    mma16(acc[mt][2 * ntp],     af[mt][0], af[mt][1], af[mt][2], af[mt][3], b0a, b1a);
                    mma16(acc[mt][2 * ntp + 1], af[mt][0], af[mt][1], af[mt][2], af[mt][3], b0b, b1b);
                }
            }
        }
        __syncthreads();
        if (t + 3 < T) { load_tiles((t + 3) * 32, p); cp_commit(); }
    }

    // Epilogue: + bias, pack bf16, store qkv
#pragma unroll
    for (int mt = 0; mt < 4; mt++) {
        int r0 = m0 + wm * 64 + mt * 16 + g;
#pragma unroll
        for (int nt = 0; nt < 8; nt++) {
            int c = n0 + wn * 64 + nt * 8 + 2 * q;
            float bx = bias[c], by = bias[c + 1];
            *(unsigned*)&g_qkvb[((size_t)b * S_ + r0) * N3_ + c] =
                pk(acc[mt][nt][0] + bx, acc[mt][nt][1] + by);
            *(unsigned*)&g_qkvb[((size_t)b * S_ + r0 + 8) * N3_ + c] =
                pk(acc[mt][nt][2] + bx, acc[mt][nt][3] + by);
        }
    }
}

// ---------------------------------------------------------------------------
// Attention: block = (b, h, 128-query tile); 8 warps x 16 q-rows (one m16).
// bf16 mma m16n8k16; Q in register A-frags; P converted C-frag -> A-frag in
// registers (no smem round-trip). K/V double-buffered cp.async.
// Strides 72 elems (144B, ==16 mod 128): ldmatrix conflict-free.
// ---------------------------------------------------------------------------
#define STKV 72
#define KV_ST (64 * STKV)
#define ATT_SMEM ((4 * KV_ST + 128 * STKV) * 2)

__global__ __launch_bounds__(256) void attn_kernel()
{
    extern __shared__ uint16_t sm16[];
    uint16_t* Qsm = sm16 + 4 * KV_ST;

    const int b  = blockIdx.z;
    const int h  = blockIdx.y;
    const int q0 = blockIdx.x * 128;

    const int tid = threadIdx.x, lane = tid & 31, warpId = tid >> 5;
    const int g = lane >> 2, q = lane & 3;
    const int wbase = warpId * 16;

    const int rk = (lane & 7) + 8 * ((lane >> 3) & 1);
    const int ck = 8 * (lane >> 4);

    const uint16_t* base = g_qkvb + (size_t)b * S_ * N3_ + h * 192;

    auto load_kv = [&](int kt, int p) {
        uint16_t* K = sm16 + p * KV_ST;
        uint16_t* V = sm16 + 2 * KV_ST + p * KV_ST;
#pragma unroll
        for (int i = 0; i < 2; i++) {
            int f = tid + i * 256;             // 512 chunks: 64 x 8
            int r = f >> 3, c8 = (f & 7) << 3;
            const uint16_t* kp = base + (size_t)(kt * 64 + r) * N3_ + 64 + c8;
            cpa16(&K[r * STKV + c8], kp);
            cpa16(&V[r * STKV + c8], kp + 64);
        }
    };

    // Q tile -> smem
#pragma unroll
    for (int i = 0; i < 4; i++) {
        int f = tid + i * 256;                 // 1024 chunks: 128 x 8
        int r = f >> 3, c8 = (f & 7) << 3;
        cpa16(&Qsm[r * STKV + c8], base + (size_t)(q0 + r) * N3_ + c8);
    }
    cp_commit();
    load_kv(0, 0); cp_commit();
    load_kv(1, 1); cp_commit();

    cp_wait<2>();   // Q ready
    __syncthreads();

    unsigned qa[4][4];
#pragma unroll
    for (int ks = 0; ks < 4; ks++)
        ldsm4(qa[ks][0], qa[ks][1], qa[ks][2], qa[ks][3],
              &Qsm[(wbase + rk) * STKV + ks * 16 + ck]);

    float o[8][4];
#pragma unroll
    for (int nt = 0; nt < 8; nt++)
#pragma unroll
        for (int r = 0; r < 4; r++) o[nt][r] = 0.f;
    float mv[2] = {-1e30f, -1e30f};
    float lv[2] = {0.f, 0.f};

    for (int kt = 0; kt < 16; kt++) {
        if (kt < 15) cp_wait<1>(); else cp_wait<0>();
        __syncthreads();

        const int p = kt & 1;
        const uint16_t* Ksm = sm16 + p * KV_ST;
        const uint16_t* Vsm = sm16 + 2 * KV_ST + p * KV_ST;

        // --- S = Q @ K^T  (m16 x 64 keys per warp)
        float s[8][4];
#pragma unroll
        for (int nt = 0; nt < 8; nt++)
#pragma unroll
            for (int r = 0; r < 4; r++) s[nt][r] = 0.f;

#pragma unroll
        for (int ks = 0; ks < 4; ks++) {
#pragma unroll
            for (int ntp = 0; ntp < 4; ntp++) {
                unsigned r0, r1, r2, r3;   // b0(e0), b0(e1), b1(e0), b1(e1)
                ldsm4(r0, r1, r2, r3, &Ksm[(ntp * 16 + rk) * STKV + ks * 16 + ck]);
                mma16(s[2 * ntp],     qa[ks][0], qa[ks][1], qa[ks][2], qa[ks][3], r0, r2);
                mma16(s[2 * ntp + 1], qa[ks][0], qa[ks][1], qa[ks][2], qa[ks][3], r1, r3);
            }
        }

        // --- Online softmax (rows g / g+8; quad shuffles)
#pragma unroll
        for (int rh = 0; rh < 2; rh++) {
            const int j0 = 2 * rh, j1 = 2 * rh + 1;
            float vmax = -1e30f;
#pragma unroll
            for (int nt = 0; nt < 8; nt++) {
                s[nt][j0] *= SCALE_;
                s[nt][j1] *= SCALE_;
                vmax = fmaxf(vmax, fmaxf(s[nt][j0], s[nt][j1]));
            }
            vmax = fmaxf(vmax, __shfl_xor_sync(0xffffffffu, vmax, 1));
            vmax = fmaxf(vmax, __shfl_xor_sync(0xffffffffu, vmax, 2));
            float mn = fmaxf(mv[rh], vmax);
            float fs = __expf(mv[rh] - mn);
            float sum = 0.f;
#pragma unroll
            for (int nt = 0; nt < 8; nt++) {
                float p0 = __expf(s[nt][j0] - mn);
                float p1 = __expf(s[nt][j1] - mn);
                s[nt][j0] = p0; s[nt][j1] = p1;
                sum += p0 + p1;
            }
            sum += __shfl_xor_sync(0xffffffffu, sum, 1);
            sum += __shfl_xor_sync(0xffffffffu, sum, 2);
            lv[rh] = lv[rh] * fs + sum;
            mv[rh] = mn;
#pragma unroll
            for (int nt = 0; nt < 8; nt++) {
                o[nt][j0] *= fs;
                o[nt][j1] *= fs;
            }
        }

        // --- O += P @ V : P stays in registers (C-frag -> bf16 A-frag)
#pragma unroll
        for (int kp = 0; kp < 4; kp++) {
            unsigned a0 = pk(s[2 * kp][0],     s[2 * kp][1]);
            unsigned a1 = pk(s[2 * kp][2],     s[2 * kp][3]);
            unsigned a2 = pk(s[2 * kp + 1][0], s[2 * kp + 1][1]);
            unsigned a3 = pk(s[2 * kp + 1][2], s[2 * kp + 1][3]);
#pragma unroll
            for (int ntp = 0; ntp < 4; ntp++) {
                unsigned r0, r1, r2, r3;   // b0(d0), b1(d0), b0(d1), b1(d1)
                ldsm4t(r0, r1, r2, r3, &Vsm[(kp * 16 + rk) * STKV + ntp * 16 + ck]);
                mma16(o[2 * ntp],     a0, a1, a2, a3, r0, r1);
                mma16(o[2 * ntp + 1], a0, a1, a2, a3, r2, r3);
            }
        }
        __syncthreads();   // all reads of stage p done before refill
        if (kt + 2 < 16) { load_kv(kt + 2, p); cp_commit(); }
    }

    // --- Epilogue: normalize, pack bf16, write res[b][q][h*64 + d]
    float inv0 = 1.f / lv[0];
    float inv1 = 1.f / lv[1];
    int r0 = q0 + wbase + g;
#pragma unroll
    for (int nt = 0; nt < 8; nt++) {
        int col = h * 64 + nt * 8 + 2 * q;
        *(unsigned*)&g_resb[((size_t)b * S_ + r0) * INNER_ + col] =
            pk(o[nt][0] * inv0, o[nt][1] * inv0);
        *(unsigned*)&g_resb[((size_t)b * S_ + r0 + 8) * INNER_ + col] =
            pk(o[nt][2] * inv1, o[nt][3] * inv1);
    }
}

// ---------------------------------------------------------------------------
// GEMM3: out[b][c][s] = sum_k res[b][s][k] * W_out[k][c] + b_out[c] + x[b][c][s]
// Block 128(c) x 256(s) x BK=32. B tile stored n-major [256][40] (non-trans
// ldmatrix needs k contiguous — res already is). fp32 epilogue + residual.
// ---------------------------------------------------------------------------
#define STB3 40
#define B3_ST (256 * STB3)
#define G3_SMEM (3 * (A_ST + B3_ST) * 2)

__global__ __launch_bounds__(256) void gemm_out_kernel(
    const uint16_t* __restrict__ Wo, const float* __restrict__ bo,
    const float* __restrict__ x, float* __restrict__ out)
{
    extern __shared__ uint16_t sm16[];

    const int b  = blockIdx.z;
    const int c0 = blockIdx.x * 128;
    const int s0 = blockIdx.y * 256;

    const int tid = threadIdx.x, lane = tid & 31, warpId = tid >> 5;
    const int g = lane >> 2, q = lane & 3;
    const int wm = warpId & 1, wn = warpId >> 1;

    const int ra = (lane & 7) + 8 * (lane >> 4);
    const int ca = 8 * ((lane >> 3) & 1);

    const uint16_t* resb = g_resb + (size_t)b * S_ * INNER_;

    float acc[4][8][4];
#pragma unroll
    for (int mt = 0; mt < 4; mt++)
#pragma unroll
        for (int nt = 0; nt < 8; nt++)
#pragma unroll
            for (int r = 0; r < 4; r++) acc[mt][nt][r] = 0.f;

    auto load_tiles = [&](int k0, int p) {
        uint16_t* A  = sm16 + p * (A_ST + B3_ST);
        uint16_t* Bn = A + A_ST;
#pragma unroll
        for (int i = 0; i < 2; i++) {
            int f = tid + i * 256;            // 512 chunks: 32 x 16
            int kk = f >> 4, m8 = (f & 15) << 3;
            cpa16(&A[kk * STA + m8], Wo + (size_t)(k0 + kk) * C_ + c0 + m8);
        }
#pragma unroll
        for (int i = 0; i < 4; i++) {
            int f = tid + i * 256;            // 1024 chunks: 256 x 4
            int nn = f >> 2, k8 = (f & 3) << 3;
            cpa16(&Bn[nn * STB3 + k8], resb + (size_t)(s0 + nn) * INNER_ + k0 + k8);
        }
    };

    load_tiles(0, 0);  cp_commit();
    load_tiles(32, 1); cp_commit();
    load_tiles(64, 2); cp_commit();

    const int T = INNER_ / 32;   // 16
    for (int t = 0; t < T; t++) {
        if (t + 2 < T) cp_wait<2>(); else if (t + 1 < T) cp_wait<1>(); else cp_wait<0>();
        __syncthreads();

        const int p = t % 3;
        const uint16_t* A  = sm16 + p * (A_ST + B3_ST);
        const uint16_t* Bn = A + A_ST;

#pragma unroll
        for (int ks = 0; ks < 32; ks += 16) {
            unsigned af[4][4];
#pragma unroll
            for (int mt = 0; mt < 4; mt++)
                ldsm4t(af[mt][0], af[mt][1], af[mt][2], af[mt][3],
                       &A[(ks + ra) * STA + wm * 64 + mt * 16 + ca]);
#pragma unroll
            for (int ntp = 0; ntp < 4; ntp++) {
                unsigned r0, r1, r2, r3;   // b0(n0), b1(n0), b0(n1), b1(n1)
                ldsm4(r0, r1, r2, r3,
                      &Bn[(wn * 64 + ntp * 16 + ra) * STB3 + ks + ca]);
#pragma unroll
                for (int mt = 0; mt < 4; mt++) {
                    mma16(acc[mt][2 * ntp],     af[mt][0], af[mt][1], af[mt][2], af[mt][3], r0, r1);
                    mma16(acc[mt][2 * ntp + 1], af[mt][0], af[mt][1], af[mt][2], af[mt][3], r2, r3);
                }
            }
        }
        __syncthreads();
        if (t + 3 < T) { load_tiles((t + 3) * 32, p); cp_commit(); }
    }

    const float* xb = x + (size_t)b * C_ * S_;
    float* ob = out + (size_t)b * C_ * S_;
#pragma unroll
    for (int mt = 0; mt < 4; mt++) {
        int cc0 = c0 + wm * 64 + mt * 16 + g;
        float bias0 = __ldg(bo + cc0);
        float bias1 = __ldg(bo + cc0 + 8);
#pragma unroll
        for (int nt = 0; nt < 8; nt++) {
            int ss = s0 + wn * 64 + nt * 8 + 2 * q;
            float2 x0 = *(const float2*)(xb + (size_t)cc0 * S_ + ss);
            float2 x1 = *(const float2*)(xb + (size_t)(cc0 + 8) * S_ + ss);
            *(float2*)(ob + (size_t)cc0 * S_ + ss) =
                make_float2(acc[mt][nt][0] + bias0 + x0.x, acc[mt][nt][1] + bias0 + x0.y);
            *(float2*)(ob + (size_t)(cc0 + 8) * S_ + ss) =
                make_float2(acc[mt][nt][2] + bias1 + x1.x, acc[mt][nt][3] + bias1 + x1.y);
        }
    }
}

// ---------------------------------------------------------------------------
extern "C" void kernel_launch(void* const* d_in, const int* in_sizes, int n_in,
                              void* d_out, int out_size)
{
    const float* x  = (const float*)d_in[0];
    const float* Wp = (const float*)d_in[1];
    const float* bp = (const float*)d_in[2];
    const float* Wo = (const float*)d_in[3];
    const float* bo = (const float*)d_in[4];
    float* out = (float*)d_out;

    cudaFuncSetAttribute(gemm_qkv_kernel, cudaFuncAttributeMaxDynamicSharedMemorySize, G1_SMEM);
    cudaFuncSetAttribute(attn_kernel,     cudaFuncAttributeMaxDynamicSharedMemorySize, ATT_SMEM);
    cudaFuncSetAttribute(gemm_out_kernel, cudaFuncAttributeMaxDynamicSharedMemorySize, G3_SMEM);

    uint16_t *xb, *wpb, *wob;
    cudaGetSymbolAddress((void**)&xb,  g_xb);
    cudaGetSymbolAddress((void**)&wpb, g_wpb);
    cudaGetSymbolAddress((void**)&wob, g_wob);

    // Stage 0: fp32 -> bf16 (rn)
    const int nx  = B_ * C_ * S_ / 4;
    const int nwp = C_ * N3_ / 4;
    const int nwo = INNER_ * C_ / 4;
    to_bf16_kernel<<<(nx  + 255) / 256, 256>>>((const float4*)x,  (uint2*)xb,  nx);
    to_bf16_kernel<<<(nwp + 255) / 256, 256>>>((const float4*)Wp, (uint2*)wpb, nwp);
    to_bf16_kernel<<<(nwo + 255) / 256, 256>>>((const float4*)Wo, (uint2*)wob, nwo);

    // Stage 1: QKV projection (bf16 tensor)
    gemm_qkv_kernel<<<dim3(S_ / 128, N3_ / 256, B_), 256, G1_SMEM>>>(xb, wpb, bp);

    // Stage 2: fused flash attention (bf16 tensor)
    attn_kernel<<<dim3(S_ / 128, H_, B_), 256, ATT_SMEM>>>();

    // Stage 3: output projection + bias + residual + transpose
    gemm_out_kernel<<<dim3(C_ / 128, S_ / 256, B_), 256, G3_SMEM>>>(wob, bo, x, out);
}

// round 7
// speedup vs baseline: 7.6902x; 1.1734x over previous
#include <cuda_runtime.h>
#include <cstdint>

#define B_     16
#define C_     512
#define S_     1024
#define H_     8
#define DH_    64
#define N3_    1536
#define INNER_ 512
#define SCALE_ 0.125f

// bf16 scratch (allocation-free rule: __device__ globals)
__device__ uint16_t g_xb [(size_t)B_ * C_ * S_];      // x  -> bf16 (b,c,s)
__device__ uint16_t g_wpb[(size_t)C_ * N3_];          // W_proj bf16
__device__ uint16_t g_wob[(size_t)INNER_ * C_];       // W_out bf16
__device__ uint16_t g_qkvb[(size_t)B_ * S_ * N3_];    // qkv bf16 (b,s,1536)
__device__ uint16_t g_resb[(size_t)B_ * S_ * INNER_]; // attn out bf16 (b,s,512)

// ---------------------------------------------------------------------------
// helpers
// ---------------------------------------------------------------------------
__device__ __forceinline__ unsigned pk(float lo, float hi) {  // bf16x2(lo,hi)
    unsigned r;
    asm("cvt.rn.bf16x2.f32 %0, %1, %2;" : "=r"(r) : "f"(hi), "f"(lo));
    return r;
}

// D += A(16x16) * B(16x8)  bf16 -> f32
__device__ __forceinline__ void mma16(float* c,
                                      unsigned a0, unsigned a1, unsigned a2, unsigned a3,
                                      unsigned b0, unsigned b1) {
    asm volatile(
        "mma.sync.aligned.m16n8k16.row.col.f32.bf16.bf16.f32 "
        "{%0,%1,%2,%3}, {%4,%5,%6,%7}, {%8,%9}, {%0,%1,%2,%3};\n"
        : "+f"(c[0]), "+f"(c[1]), "+f"(c[2]), "+f"(c[3])
        : "r"(a0), "r"(a1), "r"(a2), "r"(a3), "r"(b0), "r"(b1));
}

__device__ __forceinline__ void ldsm4(unsigned& r0, unsigned& r1, unsigned& r2, unsigned& r3,
                                      const uint16_t* p) {
    unsigned a = (unsigned)__cvta_generic_to_shared(p);
    asm volatile("ldmatrix.sync.aligned.m8n8.x4.shared.b16 {%0,%1,%2,%3}, [%4];\n"
                 : "=r"(r0), "=r"(r1), "=r"(r2), "=r"(r3) : "r"(a));
}
__device__ __forceinline__ void ldsm4t(unsigned& r0, unsigned& r1, unsigned& r2, unsigned& r3,
                                       const uint16_t* p) {
    unsigned a = (unsigned)__cvta_generic_to_shared(p);
    asm volatile("ldmatrix.sync.aligned.m8n8.x4.trans.shared.b16 {%0,%1,%2,%3}, [%4];\n"
                 : "=r"(r0), "=r"(r1), "=r"(r2), "=r"(r3) : "r"(a));
}

__device__ __forceinline__ void cpa16(void* dst, const void* src) {
    unsigned d = (unsigned)__cvta_generic_to_shared(dst);
    asm volatile("cp.async.cg.shared.global [%0], [%1], 16;\n" :: "r"(d), "l"(src));
}
__device__ __forceinline__ void cp_commit() { asm volatile("cp.async.commit_group;\n"); }
template <int N> __device__ __forceinline__ void cp_wait() {
    asm volatile("cp.async.wait_group %0;\n" :: "n"(N));
}

// ---------------------------------------------------------------------------
// Prep: fp32 -> bf16 (round-to-nearest)
// ---------------------------------------------------------------------------
__global__ __launch_bounds__(256) void to_bf16_kernel(
    const float4* __restrict__ in, uint2* __restrict__ out, int n4)
{
    int i = blockIdx.x * blockDim.x + threadIdx.x;
    if (i < n4) {
        float4 v = in[i];
        out[i] = make_uint2(pk(v.x, v.y), pk(v.z, v.w));
    }
}

// ---------------------------------------------------------------------------
// GEMM1: qkv[b][s][n] = sum_c x[b][c][s] * W_proj[c][n] + b_proj[n]   (bf16 MMA)
// Block 128(m) x 128(n) x BK=32. 8 warps = 4(m) x 2(n); warp tile 32x64.
// 3-stage cp.async pipeline; 2 CTAs/SM (launch_bounds cap).
// Strides 136 elems (272B == 16 mod 128 -> ldmatrix conflict-free).
// ---------------------------------------------------------------------------
#define STA  136
#define A_ST (32 * STA)
#define G1_SMEM (3 * (2 * A_ST) * 2)   // A + B per stage, 3 stages, bf16

__global__ __launch_bounds__(256, 2) void gemm_qkv_kernel(
    const uint16_t* __restrict__ x, const uint16_t* __restrict__ W,
    const float* __restrict__ bias)
{
    extern __shared__ uint16_t sm16[];

    const int b  = blockIdx.z;
    const int m0 = blockIdx.x * 128;
    const int n0 = blockIdx.y * 128;
    const uint16_t* xb = x + (size_t)b * C_ * S_;

    const int tid = threadIdx.x, lane = tid & 31, warpId = tid >> 5;
    const int g = lane >> 2, q = lane & 3;
    const int wm = warpId & 3, wn = warpId >> 2;   // 4(m) x 2(n)

    const int ra = (lane & 7) + 8 * (lane >> 4);         // trans row(k)
    const int ca = 8 * ((lane >> 3) & 1);                // trans col(m)
    const int rk = (lane & 7) + 8 * ((lane >> 3) & 1);   // B-trans row(k)
    const int ck = 8 * (lane >> 4);                      // B-trans col(n)

    float acc[2][8][4];
#pragma unroll
    for (int mt = 0; mt < 2; mt++)
#pragma unroll
        for (int nt = 0; nt < 8; nt++)
#pragma unroll
            for (int r = 0; r < 4; r++) acc[mt][nt][r] = 0.f;

    auto load_tiles = [&](int k0, int p) {
        uint16_t* A  = sm16 + p * 2 * A_ST;
        uint16_t* Bv = A + A_ST;
#pragma unroll
        for (int i = 0; i < 2; i++) {
            int f = tid + i * 256;            // 512 chunks: 32k x 16
            int kk = f >> 4, m8 = (f & 15) << 3;
            cpa16(&A[kk * STA + m8], xb + (size_t)(k0 + kk) * S_ + m0 + m8);
            cpa16(&Bv[kk * STA + m8], W + (size_t)(k0 + kk) * N3_ + n0 + m8);
        }
    };

    load_tiles(0, 0);  cp_commit();
    load_tiles(32, 1); cp_commit();
    load_tiles(64, 2); cp_commit();

    const int T = C_ / 32;   // 16
    for (int t = 0; t < T; t++) {
        if (t + 2 < T) cp_wait<2>(); else if (t + 1 < T) cp_wait<1>(); else cp_wait<0>();
        __syncthreads();

        const int p = t % 3;
        const uint16_t* A  = sm16 + p * 2 * A_ST;
        const uint16_t* Bv = A + A_ST;

#pragma unroll
        for (int ks = 0; ks < 32; ks += 16) {
            unsigned af[2][4];
#pragma unroll
            for (int mt = 0; mt < 2; mt++)
                ldsm4t(af[mt][0], af[mt][1], af[mt][2], af[mt][3],
                       &A[(ks + ra) * STA + wm * 32 + mt * 16 + ca]);
#pragma unroll
            for (int ntp = 0; ntp < 4; ntp++) {
                unsigned b0a, b1a, b0b, b1b;
                ldsm4t(b0a, b1a, b0b, b1b,
                       &Bv[(ks + rk) * STA + wn * 64 + ntp * 16 + ck]);
#pragma unroll
                for (int mt = 0; mt < 2; mt++) {
                    mma16(acc[mt][2 * ntp],     af[mt][0], af[mt][1], af[mt][2], af[mt][3], b0a, b1a);
                    mma16(acc[mt][2 * ntp + 1], af[mt][0], af[mt][1], af[mt][2], af[mt][3], b0b, b1b);
                }
            }
        }
        __syncthreads();
        if (t + 3 < T) { load_tiles((t + 3) * 32, p); cp_commit(); }
    }

#pragma unroll
    for (int mt = 0; mt < 2; mt++) {
        int r0 = m0 + wm * 32 + mt * 16 + g;
#pragma unroll
        for (int nt = 0; nt < 8; nt++) {
            int c = n0 + wn * 64 + nt * 8 + 2 * q;
            float bx = bias[c], by = bias[c + 1];
            *(unsigned*)&g_qkvb[((size_t)b * S_ + r0) * N3_ + c] =
                pk(acc[mt][nt][0] + bx, acc[mt][nt][1] + by);
            *(unsigned*)&g_qkvb[((size_t)b * S_ + r0 + 8) * N3_ + c] =
                pk(acc[mt][nt][2] + bx, acc[mt][nt][3] + by);
        }
    }
}

// ---------------------------------------------------------------------------
// Attention: block = (b, h, 128-query tile); 8 warps x 16 q-rows (one m16).
// P packed to bf16 A-frags right after softmax (frees s[] -> fits 128 regs,
// 2 CTAs/SM). K/V double-buffered cp.async, stride 72 (conflict-free ldsm).
// ---------------------------------------------------------------------------
#define STKV 72
#define KV_ST (64 * STKV)
#define ATT_SMEM ((4 * KV_ST + 128 * STKV) * 2)

__global__ __launch_bounds__(256, 2) void attn_kernel()
{
    extern __shared__ uint16_t sm16[];
    uint16_t* Qsm = sm16 + 4 * KV_ST;

    const int b  = blockIdx.z;
    const int h  = blockIdx.y;
    const int q0 = blockIdx.x * 128;

    const int tid = threadIdx.x, lane = tid & 31, warpId = tid >> 5;
    const int g = lane >> 2, q = lane & 3;
    const int wbase = warpId * 16;

    const int rk = (lane & 7) + 8 * ((lane >> 3) & 1);
    const int ck = 8 * (lane >> 4);

    const uint16_t* base = g_qkvb + (size_t)b * S_ * N3_ + h * 192;

    auto load_kv = [&](int kt, int p) {
        uint16_t* K = sm16 + p * KV_ST;
        uint16_t* V = sm16 + 2 * KV_ST + p * KV_ST;
#pragma unroll
        for (int i = 0; i < 2; i++) {
            int f = tid + i * 256;
            int r = f >> 3, c8 = (f & 7) << 3;
            const uint16_t* kp = base + (size_t)(kt * 64 + r) * N3_ + 64 + c8;
            cpa16(&K[r * STKV + c8], kp);
            cpa16(&V[r * STKV + c8], kp + 64);
        }
    };

#pragma unroll
    for (int i = 0; i < 4; i++) {
        int f = tid + i * 256;
        int r = f >> 3, c8 = (f & 7) << 3;
        cpa16(&Qsm[r * STKV + c8], base + (size_t)(q0 + r) * N3_ + c8);
    }
    cp_commit();
    load_kv(0, 0); cp_commit();
    load_kv(1, 1); cp_commit();

    cp_wait<2>();
    __syncthreads();

    unsigned qa[4][4];
#pragma unroll
    for (int ks = 0; ks < 4; ks++)
        ldsm4(qa[ks][0], qa[ks][1], qa[ks][2], qa[ks][3],
              &Qsm[(wbase + rk) * STKV + ks * 16 + ck]);

    float o[8][4];
#pragma unroll
    for (int nt = 0; nt < 8; nt++)
#pragma unroll
        for (int r = 0; r < 4; r++) o[nt][r] = 0.f;
    float mv[2] = {-1e30f, -1e30f};
    float lv[2] = {0.f, 0.f};

    for (int kt = 0; kt < 16; kt++) {
        if (kt < 15) cp_wait<1>(); else cp_wait<0>();
        __syncthreads();

        const int p = kt & 1;
        const uint16_t* Ksm = sm16 + p * KV_ST;
        const uint16_t* Vsm = sm16 + 2 * KV_ST + p * KV_ST;

        // --- S = Q @ K^T  (m16 x 64 keys per warp)
        float s[8][4];
#pragma unroll
        for (int nt = 0; nt < 8; nt++)
#pragma unroll
            for (int r = 0; r < 4; r++) s[nt][r] = 0.f;

#pragma unroll
        for (int ks = 0; ks < 4; ks++) {
#pragma unroll
            for (int ntp = 0; ntp < 4; ntp++) {
                unsigned r0, r1, r2, r3;
                ldsm4(r0, r1, r2, r3, &Ksm[(ntp * 16 + rk) * STKV + ks * 16 + ck]);
                mma16(s[2 * ntp],     qa[ks][0], qa[ks][1], qa[ks][2], qa[ks][3], r0, r2);
                mma16(s[2 * ntp + 1], qa[ks][0], qa[ks][1], qa[ks][2], qa[ks][3], r1, r3);
            }
        }

        // --- Online softmax (rows g / g+8; quad shuffles)
#pragma unroll
        for (int rh = 0; rh < 2; rh++) {
            const int j0 = 2 * rh, j1 = 2 * rh + 1;
            float vmax = -1e30f;
#pragma unroll
            for (int nt = 0; nt < 8; nt++) {
                s[nt][j0] *= SCALE_;
                s[nt][j1] *= SCALE_;
                vmax = fmaxf(vmax, fmaxf(s[nt][j0], s[nt][j1]));
            }
            vmax = fmaxf(vmax, __shfl_xor_sync(0xffffffffu, vmax, 1));
            vmax = fmaxf(vmax, __shfl_xor_sync(0xffffffffu, vmax, 2));
            float mn = fmaxf(mv[rh], vmax);
            float fs = __expf(mv[rh] - mn);
            float sum = 0.f;
#pragma unroll
            for (int nt = 0; nt < 8; nt++) {
                float p0 = __expf(s[nt][j0] - mn);
                float p1 = __expf(s[nt][j1] - mn);
                s[nt][j0] = p0; s[nt][j1] = p1;
                sum += p0 + p1;
            }
            sum += __shfl_xor_sync(0xffffffffu, sum, 1);
            sum += __shfl_xor_sync(0xffffffffu, sum, 2);
            lv[rh] = lv[rh] * fs + sum;
            mv[rh] = mn;
#pragma unroll
            for (int nt = 0; nt < 8; nt++) {
                o[nt][j0] *= fs;
                o[nt][j1] *= fs;
            }
        }

        // --- Pack P -> bf16 A-frags now (frees s[] before PV loop)
        unsigned pa[4][4];
#pragma unroll
        for (int kp = 0; kp < 4; kp++) {
            pa[kp][0] = pk(s[2 * kp][0],     s[2 * kp][1]);
            pa[kp][1] = pk(s[2 * kp][2],     s[2 * kp][3]);
            pa[kp][2] = pk(s[2 * kp + 1][0], s[2 * kp + 1][1]);
            pa[kp][3] = pk(s[2 * kp + 1][2], s[2 * kp + 1][3]);
        }

        // --- O += P @ V
#pragma unroll
        for (int kp = 0; kp < 4; kp++) {
#pragma unroll
            for (int ntp = 0; ntp < 4; ntp++) {
                unsigned r0, r1, r2, r3;
                ldsm4t(r0, r1, r2, r3, &Vsm[(kp * 16 + rk) * STKV + ntp * 16 + ck]);
                mma16(o[2 * ntp],     pa[kp][0], pa[kp][1], pa[kp][2], pa[kp][3], r0, r1);
                mma16(o[2 * ntp + 1], pa[kp][0], pa[kp][1], pa[kp][2], pa[kp][3], r2, r3);
            }
        }
        __syncthreads();
        if (kt + 2 < 16) { load_kv(kt + 2, p); cp_commit(); }
    }

    float inv0 = 1.f / lv[0];
    float inv1 = 1.f / lv[1];
    int r0 = q0 + wbase + g;
#pragma unroll
    for (int nt = 0; nt < 8; nt++) {
        int col = h * 64 + nt * 8 + 2 * q;
        *(unsigned*)&g_resb[((size_t)b * S_ + r0) * INNER_ + col] =
            pk(o[nt][0] * inv0, o[nt][1] * inv0);
        *(unsigned*)&g_resb[((size_t)b * S_ + r0 + 8) * INNER_ + col] =
            pk(o[nt][2] * inv1, o[nt][3] * inv1);
    }
}

// ---------------------------------------------------------------------------
// GEMM3: out[b][c][s] = sum_k res[b][s][k] * W_out[k][c] + b_out[c] + x[b][c][s]
// Block 128(c) x 128(s) x BK=32; 2 CTAs/SM. B tile n-major [128][40].
// ---------------------------------------------------------------------------
#define STB3 40
#define B3_ST (128 * STB3)
#define G3_SMEM (3 * (A_ST + B3_ST) * 2)

__global__ __launch_bounds__(256, 2) void gemm_out_kernel(
    const uint16_t* __restrict__ Wo, const float* __restrict__ bo,
    const float* __restrict__ x, float* __restrict__ out)
{
    extern __shared__ uint16_t sm16[];

    const int b  = blockIdx.z;
    const int c0 = blockIdx.x * 128;
    const int s0 = blockIdx.y * 128;

    const int tid = threadIdx.x, lane = tid & 31, warpId = tid >> 5;
    const int g = lane >> 2, q = lane & 3;
    const int wm = warpId & 3, wn = warpId >> 2;   // 4(m) x 2(n)

    const int ra = (lane & 7) + 8 * (lane >> 4);
    const int ca = 8 * ((lane >> 3) & 1);

    const uint16_t* resb = g_resb + (size_t)b * S_ * INNER_;

    float acc[2][8][4];
#pragma unroll
    for (int mt = 0; mt < 2; mt++)
#pragma unroll
        for (int nt = 0; nt < 8; nt++)
#pragma unroll
            for (int r = 0; r < 4; r++) acc[mt][nt][r] = 0.f;

    auto load_tiles = [&](int k0, int p) {
        uint16_t* A  = sm16 + p * (A_ST + B3_ST);
        uint16_t* Bn = A + A_ST;
#pragma unroll
        for (int i = 0; i < 2; i++) {
            int f = tid + i * 256;            // 512 chunks: 32k x 16
            int kk = f >> 4, m8 = (f & 15) << 3;
            cpa16(&A[kk * STA + m8], Wo + (size_t)(k0 + kk) * C_ + c0 + m8);
        }
#pragma unroll
        for (int i = 0; i < 2; i++) {
            int f = tid + i * 256;            // 512 chunks: 128s x 4
            int nn = f >> 2, k8 = (f & 3) << 3;
            cpa16(&Bn[nn * STB3 + k8], resb + (size_t)(s0 + nn) * INNER_ + k0 + k8);
        }
    };

    load_tiles(0, 0);  cp_commit();
    load_tiles(32, 1); cp_commit();
    load_tiles(64, 2); cp_commit();

    const int T = INNER_ / 32;   // 16
    for (int t = 0; t < T; t++) {
        if (t + 2 < T) cp_wait<2>(); else if (t + 1 < T) cp_wait<1>(); else cp_wait<0>();
        __syncthreads();

        const int p = t % 3;
        const uint16_t* A  = sm16 + p * (A_ST + B3_ST);
        const uint16_t* Bn = A + A_ST;

#pragma unroll
        for (int ks = 0; ks < 32; ks += 16) {
            unsigned af[2][4];
#pragma unroll
            for (int mt = 0; mt < 2; mt++)
                ldsm4t(af[mt][0], af[mt][1], af[mt][2], af[mt][3],
                       &A[(ks + ra) * STA + wm * 32 + mt * 16 + ca]);
#pragma unroll
            for (int ntp = 0; ntp < 4; ntp++) {
                unsigned r0, r1, r2, r3;
                ldsm4(r0, r1, r2, r3,
                      &Bn[(wn * 64 + ntp * 16 + ra) * STB3 + ks + ca]);
#pragma unroll
                for (int mt = 0; mt < 2; mt++) {
                    mma16(acc[mt][2 * ntp],     af[mt][0], af[mt][1], af[mt][2], af[mt][3], r0, r1);
                    mma16(acc[mt][2 * ntp + 1], af[mt][0], af[mt][1], af[mt][2], af[mt][3], r2, r3);
                }
            }
        }
        __syncthreads();
        if (t + 3 < T) { load_tiles((t + 3) * 32, p); cp_commit(); }
    }

    const float* xb = x + (size_t)b * C_ * S_;
    float* ob = out + (size_t)b * C_ * S_;
#pragma unroll
    for (int mt = 0; mt < 2; mt++) {
        int cc0 = c0 + wm * 32 + mt * 16 + g;
        float bias0 = __ldg(bo + cc0);
        float bias1 = __ldg(bo + cc0 + 8);
#pragma unroll
        for (int nt = 0; nt < 8; nt++) {
            int ss = s0 + wn * 64 + nt * 8 + 2 * q;
            float2 x0 = *(const float2*)(xb + (size_t)cc0 * S_ + ss);
            float2 x1 = *(const float2*)(xb + (size_t)(cc0 + 8) * S_ + ss);
            *(float2*)(ob + (size_t)cc0 * S_ + ss) =
                make_float2(acc[mt][nt][0] + bias0 + x0.x, acc[mt][nt][1] + bias0 + x0.y);
            *(float2*)(ob + (size_t)(cc0 + 8) * S_ + ss) =
                make_float2(acc[mt][nt][2] + bias1 + x1.x, acc[mt][nt][3] + bias1 + x1.y);
        }
    }
}

// ---------------------------------------------------------------------------
extern "C" void kernel_launch(void* const* d_in, const int* in_sizes, int n_in,
                              void* d_out, int out_size)
{
    const float* x  = (const float*)d_in[0];
    const float* Wp = (const float*)d_in[1];
    const float* bp = (const float*)d_in[2];
    const float* Wo = (const float*)d_in[3];
    const float* bo = (const float*)d_in[4];
    float* out = (float*)d_out;

    cudaFuncSetAttribute(gemm_qkv_kernel, cudaFuncAttributeMaxDynamicSharedMemorySize, G1_SMEM);
    cudaFuncSetAttribute(attn_kernel,     cudaFuncAttributeMaxDynamicSharedMemorySize, ATT_SMEM);
    cudaFuncSetAttribute(gemm_out_kernel, cudaFuncAttributeMaxDynamicSharedMemorySize, G3_SMEM);

    uint16_t *xb, *wpb, *wob;
    cudaGetSymbolAddress((void**)&xb,  g_xb);
    cudaGetSymbolAddress((void**)&wpb, g_wpb);
    cudaGetSymbolAddress((void**)&wob, g_wob);

    // Stage 0: fp32 -> bf16 (rn)
    const int nx  = B_ * C_ * S_ / 4;
    const int nwp = C_ * N3_ / 4;
    const int nwo = INNER_ * C_ / 4;
    to_bf16_kernel<<<(nx  + 255) / 256, 256>>>((const float4*)x,  (uint2*)xb,  nx);
    to_bf16_kernel<<<(nwp + 255) / 256, 256>>>((const float4*)Wp, (uint2*)wpb, nwp);
    to_bf16_kernel<<<(nwo + 255) / 256, 256>>>((const float4*)Wo, (uint2*)wob, nwo);

    // Stage 1: QKV projection (bf16 mma.sync, 2 CTAs/SM)
    gemm_qkv_kernel<<<dim3(S_ / 128, N3_ / 128, B_), 256, G1_SMEM>>>(xb, wpb, bp);

    // Stage 2: fused flash attention (bf16 mma.sync, 2 CTAs/SM)
    attn_kernel<<<dim3(S_ / 128, H_, B_), 256, ATT_SMEM>>>();

    // Stage 3: output projection + bias + residual + transpose (2 CTAs/SM)
    gemm_out_kernel<<<dim3(C_ / 128, S_ / 128, B_), 256, G3_SMEM>>>(Wo ? wob : wob, bo, x, out);
}